// round 1
// baseline (speedup 1.0000x reference)
#include <cuda_runtime.h>
#include <math.h>

#define NN   100000
#define EE   1600000
#define ENE  1700000      // E + N self loops
#define HH   4
#define CC   128
#define DD   512
#define FIN  182
#define NEG_SLOPE 0.2f
#define LN_EPS 1e-5f

// ---------------- scratch (device globals: sanctioned workaround) ----------------
__device__ float g_bufA[(size_t)NN * DD];     // 204.8 MB
__device__ float g_bufB[(size_t)NN * DD];     // 204.8 MB
__device__ float g_ssrc[NN * HH];
__device__ float g_sdst[NN * HH];
__device__ float g_emax[NN * HH];
__device__ float g_denom[NN * HH];
__device__ float g_p[(size_t)ENE * HH];       // 27.2 MB (raw e, then p)
__device__ int   g_is64;

// ---------------- helpers ----------------
__device__ __forceinline__ float atomicMaxFloat(float* addr, float value) {
    // classic signed/unsigned bit trick; init must be -inf (0xFF800000)
    if (value >= 0.0f)
        return __int_as_float(atomicMax((int*)addr, __float_as_int(value)));
    else
        return __uint_as_float(atomicMin((unsigned int*)addr, __float_as_uint(value)));
}

__device__ __forceinline__ void load_edge(const void* ei, int ed, int& s, int& d) {
    if (ed >= EE) { s = d = ed - EE; return; }           // self loops appended last
    if (g_is64) {
        const long long* p = (const long long*)ei;
        s = (int)p[ed]; d = (int)p[EE + ed];
    } else {
        const int* p = (const int*)ei;
        s = p[ed]; d = p[EE + ed];
    }
}

// Detect whether edge_index is int64 or int32: for int64 (values < 2^31, LE),
// every odd 32-bit word is zero. For random int32 node ids this is ~impossible.
__global__ void detect_idx_width(const unsigned* __restrict__ w) {
    __shared__ unsigned acc[256];
    unsigned v = 0;
    for (int i = threadIdx.x; i < 4096; i += 256)
        if (i & 1) v |= w[i];
    acc[threadIdx.x] = v;
    __syncthreads();
    for (int s = 128; s > 0; s >>= 1) {
        if (threadIdx.x < s) acc[threadIdx.x] |= acc[threadIdx.x + s];
        __syncthreads();
    }
    if (threadIdx.x == 0) g_is64 = (acc[0] == 0u) ? 1 : 0;
}

// ---------------- generic fp32 GEMM: C[M,Nc] = A[M,K] @ B[K,Nc] (+bias)(+relu) ----
// 128x128 block, BK=8, 256 threads, 8x8 per thread.
__global__ __launch_bounds__(256) void gemm128(
    const float* __restrict__ A, const float* __restrict__ B, float* __restrict__ C,
    int M, int K, int Nc, const float* __restrict__ bias, int doRelu)
{
    __shared__ float As[8][128];   // transposed A tile
    __shared__ float Bs[8][128];
    int tid = threadIdx.x;
    int tx = tid & 15, ty = tid >> 4;
    int m0 = blockIdx.y * 128, n0 = blockIdx.x * 128;

    float acc[8][8];
#pragma unroll
    for (int i = 0; i < 8; i++)
#pragma unroll
        for (int j = 0; j < 8; j++) acc[i][j] = 0.0f;

    int kt = (K + 7) / 8;
    for (int t = 0; t < kt; t++) {
        int k0 = t * 8;
        // load A tile (scalar; K=182 rows are not 16B aligned)
        {
            int i = tid * 4;
            int row = i >> 3, kk = i & 7;   // kk in {0,4}
            int gm = m0 + row;
#pragma unroll
            for (int j = 0; j < 4; j++) {
                int gk = k0 + kk + j;
                float v = 0.0f;
                if (gm < M && gk < K) v = A[(size_t)gm * K + gk];
                As[kk + j][row] = v;
            }
        }
        // load B tile (float4; Nc multiple of 128)
        {
            int i = tid * 4;
            int kk = i >> 7, col = i & 127;
            float4 v = make_float4(0.f, 0.f, 0.f, 0.f);
            if (k0 + kk < K) v = *(const float4*)(B + (size_t)(k0 + kk) * Nc + n0 + col);
            *(float4*)&Bs[kk][col] = v;
        }
        __syncthreads();
#pragma unroll
        for (int k = 0; k < 8; k++) {
            float a[8], b[8];
            *(float4*)(a)     = *(float4*)&As[k][ty * 8];
            *(float4*)(a + 4) = *(float4*)&As[k][ty * 8 + 4];
            *(float4*)(b)     = *(float4*)&Bs[k][tx * 8];
            *(float4*)(b + 4) = *(float4*)&Bs[k][tx * 8 + 4];
#pragma unroll
            for (int i = 0; i < 8; i++)
#pragma unroll
                for (int j = 0; j < 8; j++) acc[i][j] = fmaf(a[i], b[j], acc[i][j]);
        }
        __syncthreads();
    }
#pragma unroll
    for (int i = 0; i < 8; i++) {
        int gm = m0 + ty * 8 + i;
        if (gm >= M) continue;
#pragma unroll
        for (int j = 0; j < 8; j += 4) {
            int gn = n0 + tx * 8 + j;
            float4 v = make_float4(acc[i][j], acc[i][j + 1], acc[i][j + 2], acc[i][j + 3]);
            if (bias) { v.x += bias[gn]; v.y += bias[gn + 1]; v.z += bias[gn + 2]; v.w += bias[gn + 3]; }
            if (doRelu) {
                v.x = fmaxf(v.x, 0.f); v.y = fmaxf(v.y, 0.f);
                v.z = fmaxf(v.z, 0.f); v.w = fmaxf(v.w, 0.f);
            }
            *(float4*)(C + (size_t)gm * Nc + gn) = v;
        }
    }
}

// ---------------- per-node attention dot products ----------------
// one block (128 thr) per node; warp w handles head w; lane covers 4 floats
__global__ __launch_bounds__(128) void sdot_kernel(
    const float* __restrict__ feat, const float* __restrict__ asrc,
    const float* __restrict__ adst, float* __restrict__ ssrc, float* __restrict__ sdst)
{
    int n = blockIdx.x, t = threadIdx.x;
    int h = t >> 5, lane = t & 31;
    float4 v = ((const float4*)(feat + (size_t)n * DD + h * CC))[lane];
    float4 a = ((const float4*)(asrc + h * CC))[lane];
    float4 b = ((const float4*)(adst + h * CC))[lane];
    float s1 = v.x * a.x + v.y * a.y + v.z * a.z + v.w * a.w;
    float s2 = v.x * b.x + v.y * b.y + v.z * b.z + v.w * b.w;
#pragma unroll
    for (int o = 16; o > 0; o >>= 1) {
        s1 += __shfl_down_sync(0xffffffffu, s1, o);
        s2 += __shfl_down_sync(0xffffffffu, s2, o);
    }
    if (lane == 0) { ssrc[n * HH + h] = s1; sdst[n * HH + h] = s2; }
}

__global__ void init_softmax(float* __restrict__ emax, float* __restrict__ denom) {
    int i = blockIdx.x * blockDim.x + threadIdx.x;
    if (i < NN * HH) { emax[i] = -INFINITY; denom[i] = 0.0f; }
}

__global__ void zero4(float* __restrict__ p, int n4) {
    int i = blockIdx.x * blockDim.x + threadIdx.x;
    if (i < n4) ((float4*)p)[i] = make_float4(0.f, 0.f, 0.f, 0.f);
}

// ---------------- edge pass 1: raw scores + segment max ----------------
__global__ void edge_score(const void* __restrict__ ei,
                           const float* __restrict__ ssrc, const float* __restrict__ sdst,
                           float* __restrict__ eout, float* __restrict__ emax)
{
    int tid = blockIdx.x * blockDim.x + threadIdx.x;
    if (tid >= ENE * HH) return;
    int h = tid & 3, ed = tid >> 2;
    int s, d; load_edge(ei, ed, s, d);
    float v = ssrc[s * HH + h] + sdst[d * HH + h];
    v = (v > 0.0f) ? v : NEG_SLOPE * v;
    eout[tid] = v;
    atomicMaxFloat(&emax[d * HH + h], v);
}

// ---------------- edge pass 2: exp + segment sum ----------------
__global__ void edge_exp(const void* __restrict__ ei,
                         const float* __restrict__ emax, float* __restrict__ p,
                         float* __restrict__ denom)
{
    int tid = blockIdx.x * blockDim.x + threadIdx.x;
    if (tid >= ENE * HH) return;
    int h = tid & 3, ed = tid >> 2;
    int s, d; load_edge(ei, ed, s, d);
    float v = __expf(p[tid] - emax[d * HH + h]);
    p[tid] = v;
    atomicAdd(&denom[d * HH + h], v);
}

// ---------------- edge pass 3: alpha-weighted feature scatter ----------------
// one block (128 thr) per edge; thread t covers floats [4t, 4t+4); head = t>>5
__global__ __launch_bounds__(128) void edge_aggregate(
    const void* __restrict__ ei, const float* __restrict__ p,
    const float* __restrict__ denom, const float* __restrict__ feat,
    float* __restrict__ out)
{
    int ed = blockIdx.x;
    int t = threadIdx.x;
    int s, d; load_edge(ei, ed, s, d);
    int h = t >> 5;
    float alpha = p[ed * HH + h] / denom[d * HH + h];
    float4 v = *(const float4*)(feat + (size_t)s * DD + t * 4);
    v.x *= alpha; v.y *= alpha; v.z *= alpha; v.w *= alpha;
    float* dp = out + (size_t)d * DD + t * 4;
    asm volatile("red.global.add.v4.f32 [%0], {%1,%2,%3,%4};"
                 :: "l"(dp), "f"(v.x), "f"(v.y), "f"(v.z), "f"(v.w) : "memory");
}

// ---------------- bias + LayerNorm + ELU (in place) ----------------
__global__ __launch_bounds__(128) void ln_elu(
    float* __restrict__ buf, const float* __restrict__ bias,
    const float* __restrict__ g, const float* __restrict__ be)
{
    int n = blockIdx.x, t = threadIdx.x;
    int lane = t & 31, w = t >> 5;
    float4* rowp = (float4*)(buf + (size_t)n * DD);
    float4 x = rowp[t];
    float4 bb = ((const float4*)bias)[t];
    x.x += bb.x; x.y += bb.y; x.z += bb.z; x.w += bb.w;

    __shared__ float sm[4];
    float s = x.x + x.y + x.z + x.w;
#pragma unroll
    for (int o = 16; o > 0; o >>= 1) s += __shfl_down_sync(0xffffffffu, s, o);
    if (lane == 0) sm[w] = s;
    __syncthreads();
    float mu = (sm[0] + sm[1] + sm[2] + sm[3]) * (1.0f / DD);
    __syncthreads();

    float dx = x.x - mu, dy = x.y - mu, dz = x.z - mu, dw = x.w - mu;
    float ss = dx * dx + dy * dy + dz * dz + dw * dw;
#pragma unroll
    for (int o = 16; o > 0; o >>= 1) ss += __shfl_down_sync(0xffffffffu, ss, o);
    if (lane == 0) sm[w] = ss;
    __syncthreads();
    float var = (sm[0] + sm[1] + sm[2] + sm[3]) * (1.0f / DD);
    float r = rsqrtf(var + LN_EPS);

    float4 gg = ((const float4*)g)[t];
    float4 b2 = ((const float4*)be)[t];
    float4 y;
    y.x = dx * r * gg.x + b2.x;
    y.y = dy * r * gg.y + b2.y;
    y.z = dz * r * gg.z + b2.z;
    y.w = dw * r * gg.w + b2.w;
    y.x = (y.x > 0.f) ? y.x : expm1f(y.x);
    y.y = (y.y > 0.f) ? y.y : expm1f(y.y);
    y.z = (y.z > 0.f) ? y.z : expm1f(y.z);
    y.w = (y.w > 0.f) ? y.w : expm1f(y.w);
    rowp[t] = y;
}

// ---------------- final tiny projection: out[N,2] = z @ Wc2 + bc2 ----------------
__global__ void final_proj(const float* __restrict__ z, const float* __restrict__ Wc2,
                           const float* __restrict__ bc2, float* __restrict__ out)
{
    int gw = (blockIdx.x * blockDim.x + threadIdx.x) >> 5;
    int lane = threadIdx.x & 31;
    if (gw >= NN) return;
    const float* zp = z + (size_t)gw * DD;
    float s0 = 0.f, s1 = 0.f;
    for (int k = lane; k < DD; k += 32) {
        float zv = zp[k];
        s0 += zv * Wc2[2 * k];
        s1 += zv * Wc2[2 * k + 1];
    }
#pragma unroll
    for (int o = 16; o > 0; o >>= 1) {
        s0 += __shfl_down_sync(0xffffffffu, s0, o);
        s1 += __shfl_down_sync(0xffffffffu, s1, o);
    }
    if (lane == 0) { out[gw * 2] = s0 + bc2[0]; out[gw * 2 + 1] = s1 + bc2[1]; }
}

// ---------------- host orchestration ----------------
static void run_gat_layer(const void* ei, float* feat /*in: bufX*/, float* outb,
                          const float* asrc, const float* adst,
                          const float* gatb, const float* g, const float* be,
                          float* ssrc, float* sdst, float* emax, float* denom, float* pp)
{
    sdot_kernel<<<NN, 128>>>(feat, asrc, adst, ssrc, sdst);
    init_softmax<<<(NN * HH + 255) / 256, 256>>>(emax, denom);
    zero4<<<((NN * (DD / 4)) + 255) / 256, 256>>>(outb, NN * (DD / 4));
    int nthr = ENE * HH;
    edge_score<<<(nthr + 255) / 256, 256>>>(ei, ssrc, sdst, pp, emax);
    edge_exp<<<(nthr + 255) / 256, 256>>>(ei, emax, pp, denom);
    edge_aggregate<<<ENE, 128>>>(ei, pp, denom, feat, outb);
    ln_elu<<<NN, 128>>>(outb, gatb, g, be);
}

extern "C" void kernel_launch(void* const* d_in, const int* in_sizes, int n_in,
                              void* d_out, int out_size)
{
    const float* x   = (const float*)d_in[0];
    const void*  ei  = d_in[1];
    const float* W1  = (const float*)d_in[2];
    const float* as1 = (const float*)d_in[3];
    const float* ad1 = (const float*)d_in[4];
    const float* b1  = (const float*)d_in[5];
    const float* g1  = (const float*)d_in[6];
    const float* be1 = (const float*)d_in[7];
    const float* W2  = (const float*)d_in[8];
    const float* as2 = (const float*)d_in[9];
    const float* ad2 = (const float*)d_in[10];
    const float* b2  = (const float*)d_in[11];
    const float* g2  = (const float*)d_in[12];
    const float* be2 = (const float*)d_in[13];
    const float* Wc1 = (const float*)d_in[14];
    const float* bc1 = (const float*)d_in[15];
    const float* Wc2 = (const float*)d_in[16];
    const float* bc2 = (const float*)d_in[17];
    float* out = (float*)d_out;

    float *A, *B, *ssrc, *sdst, *emax, *denom, *pp;
    cudaGetSymbolAddress((void**)&A,     g_bufA);
    cudaGetSymbolAddress((void**)&B,     g_bufB);
    cudaGetSymbolAddress((void**)&ssrc,  g_ssrc);
    cudaGetSymbolAddress((void**)&sdst,  g_sdst);
    cudaGetSymbolAddress((void**)&emax,  g_emax);
    cudaGetSymbolAddress((void**)&denom, g_denom);
    cudaGetSymbolAddress((void**)&pp,    g_p);

    detect_idx_width<<<1, 256>>>((const unsigned*)ei);

    dim3 gemm_grid(DD / 128, (NN + 127) / 128);

    // layer 1: h1 = x @ W1 ; GAT ; LN ; ELU  -> features in B
    gemm128<<<gemm_grid, 256>>>(x, W1, A, NN, FIN, DD, nullptr, 0);
    run_gat_layer(ei, A, B, as1, ad1, b1, g1, be1, ssrc, sdst, emax, denom, pp);

    // layer 2: h2 = f1 @ W2 ; GAT ; LN ; ELU -> features in B
    gemm128<<<gemm_grid, 256>>>(B, W2, A, NN, DD, DD, nullptr, 0);
    run_gat_layer(ei, A, B, as2, ad2, b2, g2, be2, ssrc, sdst, emax, denom, pp);

    // classifier: z = relu(f2 @ Wc1 + bc1); out = z @ Wc2 + bc2
    gemm128<<<gemm_grid, 256>>>(B, Wc1, A, NN, DD, DD, bc1, 1);
    final_proj<<<(NN * 32 + 255) / 256, 256>>>(A, Wc2, bc2, out);
}

// round 3
// speedup vs baseline: 1.6897x; 1.6897x over previous
#include <cuda_runtime.h>
#include <math.h>

#define NN   100000
#define EE   1600000
#define ENE  1700000      // E + N self loops
#define HH   4
#define CC   128
#define DD   512
#define FIN  182
#define NEG_SLOPE 0.2f
#define LN_EPS 1e-5f

// ---------------- scratch (device globals) ----------------
__device__ float g_bufA[(size_t)NN * DD];     // 204.8 MB
__device__ float g_bufB[(size_t)NN * DD];     // 204.8 MB
__device__ float g_ssrc[NN * HH];
__device__ float g_sdst[NN * HH];
__device__ int   g_rowptr[NN + 1];
__device__ int   g_cursor[NN];
__device__ int   g_bsum[256];
__device__ int   g_csr[ENE];
__device__ int   g_is64;

// ---------------- edge decode ----------------
__device__ __forceinline__ void load_edge(const void* ei, int ed, int& s, int& d) {
    if (ed >= EE) { s = d = ed - EE; return; }           // self loops appended last
    if (g_is64) {
        const long long* p = (const long long*)ei;
        s = (int)p[ed]; d = (int)p[EE + ed];
    } else {
        const int* p = (const int*)ei;
        s = p[ed]; d = p[EE + ed];
    }
}

// int64 vs int32 detection: for little-endian int64 with values < 2^31,
// every odd 32-bit word is zero.
__global__ void detect_idx_width(const unsigned* __restrict__ w) {
    __shared__ unsigned acc[256];
    unsigned v = 0;
    for (int i = threadIdx.x; i < 4096; i += 256)
        if (i & 1) v |= w[i];
    acc[threadIdx.x] = v;
    __syncthreads();
    for (int s = 128; s > 0; s >>= 1) {
        if (threadIdx.x < s) acc[threadIdx.x] |= acc[threadIdx.x + s];
        __syncthreads();
    }
    if (threadIdx.x == 0) g_is64 = (acc[0] == 0u) ? 1 : 0;
}

// ---------------- CSR build ----------------
__global__ void init_deg(int* __restrict__ deg) {
    int i = blockIdx.x * blockDim.x + threadIdx.x;
    if (i < NN) deg[i] = 1;                              // self loop pre-counted
}

__global__ void count_deg(const void* __restrict__ ei, int* __restrict__ deg) {
    for (int ed = blockIdx.x * blockDim.x + threadIdx.x; ed < EE;
         ed += gridDim.x * blockDim.x) {
        int s, d; load_edge(ei, ed, s, d);
        atomicAdd(&deg[d], 1);
    }
}

// 1024-wide block inclusive scan -> exclusive partials + block sums
__global__ __launch_bounds__(1024) void scan1(int* __restrict__ rp, int* __restrict__ bsum) {
    __shared__ int sh[1024];
    int i = blockIdx.x * 1024 + threadIdx.x;
    int v = (i < NN) ? rp[i] : 0;
    sh[threadIdx.x] = v;
    __syncthreads();
#pragma unroll
    for (int o = 1; o < 1024; o <<= 1) {
        int t = (threadIdx.x >= o) ? sh[threadIdx.x - o] : 0;
        __syncthreads();
        sh[threadIdx.x] += t;
        __syncthreads();
    }
    if (i < NN) rp[i] = sh[threadIdx.x] - v;             // exclusive
    if (threadIdx.x == 1023) bsum[blockIdx.x] = sh[1023];
}

__global__ void scan2(int* __restrict__ bsum, int nb) {
    if (threadIdx.x == 0) {
        int acc = 0;
        for (int i = 0; i < nb; i++) { int t = bsum[i]; bsum[i] = acc; acc += t; }
    }
}

__global__ void scan3(int* __restrict__ rp, const int* __restrict__ bsum,
                      int* __restrict__ cursor) {
    int i = blockIdx.x * blockDim.x + threadIdx.x;
    if (i < NN) {
        int v = rp[i] + bsum[i >> 10];
        rp[i] = v;
        cursor[i] = v;
    }
    if (i == 0) rp[NN] = ENE;
}

__global__ void fill_csr(const void* __restrict__ ei, int* __restrict__ cursor,
                         int* __restrict__ csr) {
    for (int ed = blockIdx.x * blockDim.x + threadIdx.x; ed < ENE;
         ed += gridDim.x * blockDim.x) {
        int s, d; load_edge(ei, ed, s, d);
        int pos = atomicAdd(&cursor[d], 1);
        csr[pos] = s;
    }
}

// ---------------- fp32 GEMM: C[M,Nc] = A[M,K] @ B[K,Nc] (+bias)(+relu) ----
// 128x128 tile, BK=8, 256 threads, 8x8 per thread. AVEC=1 requires K%8==0.
template <int AVEC>
__global__ __launch_bounds__(256) void gemm128(
    const float* __restrict__ A, const float* __restrict__ B, float* __restrict__ C,
    int M, int K, int Nc, const float* __restrict__ bias, int doRelu)
{
    __shared__ float As[8][128];   // transposed A tile
    __shared__ float Bs[8][128];
    int tid = threadIdx.x;
    int tx = tid & 15, ty = tid >> 4;
    int m0 = blockIdx.y * 128, n0 = blockIdx.x * 128;

    float acc[8][8];
#pragma unroll
    for (int i = 0; i < 8; i++)
#pragma unroll
        for (int j = 0; j < 8; j++) acc[i][j] = 0.0f;

    int kt = (K + 7) / 8;
    for (int t = 0; t < kt; t++) {
        int k0 = t * 8;
        {
            int i = tid * 4;
            int row = i >> 3, kk = i & 7;   // kk in {0,4}
            int gm = m0 + row;
            if (AVEC) {
                float4 v = make_float4(0.f, 0.f, 0.f, 0.f);
                if (gm < M) v = *(const float4*)(A + (size_t)gm * K + k0 + kk);
                As[kk + 0][row] = v.x; As[kk + 1][row] = v.y;
                As[kk + 2][row] = v.z; As[kk + 3][row] = v.w;
            } else {
#pragma unroll
                for (int j = 0; j < 4; j++) {
                    int gk = k0 + kk + j;
                    float v = 0.0f;
                    if (gm < M && gk < K) v = A[(size_t)gm * K + gk];
                    As[kk + j][row] = v;
                }
            }
        }
        {
            int i = tid * 4;
            int kk = i >> 7, col = i & 127;
            float4 v = make_float4(0.f, 0.f, 0.f, 0.f);
            if (k0 + kk < K) v = *(const float4*)(B + (size_t)(k0 + kk) * Nc + n0 + col);
            *(float4*)&Bs[kk][col] = v;
        }
        __syncthreads();
#pragma unroll
        for (int k = 0; k < 8; k++) {
            float a[8], b[8];
            *(float4*)(a)     = *(float4*)&As[k][ty * 8];
            *(float4*)(a + 4) = *(float4*)&As[k][ty * 8 + 4];
            *(float4*)(b)     = *(float4*)&Bs[k][tx * 8];
            *(float4*)(b + 4) = *(float4*)&Bs[k][tx * 8 + 4];
#pragma unroll
            for (int i = 0; i < 8; i++)
#pragma unroll
                for (int j = 0; j < 8; j++) acc[i][j] = fmaf(a[i], b[j], acc[i][j]);
        }
        __syncthreads();
    }
#pragma unroll
    for (int i = 0; i < 8; i++) {
        int gm = m0 + ty * 8 + i;
        if (gm >= M) continue;
#pragma unroll
        for (int j = 0; j < 8; j += 4) {
            int gn = n0 + tx * 8 + j;
            float4 v = make_float4(acc[i][j], acc[i][j + 1], acc[i][j + 2], acc[i][j + 3]);
            if (bias) { v.x += bias[gn]; v.y += bias[gn + 1]; v.z += bias[gn + 2]; v.w += bias[gn + 3]; }
            if (doRelu) {
                v.x = fmaxf(v.x, 0.f); v.y = fmaxf(v.y, 0.f);
                v.z = fmaxf(v.z, 0.f); v.w = fmaxf(v.w, 0.f);
            }
            *(float4*)(C + (size_t)gm * Nc + gn) = v;
        }
    }
}

// ---------------- per-node attention dot products ----------------
__global__ __launch_bounds__(128) void sdot_kernel(
    const float* __restrict__ feat, const float* __restrict__ asrc,
    const float* __restrict__ adst, float* __restrict__ ssrc, float* __restrict__ sdst)
{
    int n = blockIdx.x, t = threadIdx.x;
    int h = t >> 5, lane = t & 31;
    float4 v = ((const float4*)(feat + (size_t)n * DD + h * CC))[lane];
    float4 a = ((const float4*)(asrc + h * CC))[lane];
    float4 b = ((const float4*)(adst + h * CC))[lane];
    float s1 = v.x * a.x + v.y * a.y + v.z * a.z + v.w * a.w;
    float s2 = v.x * b.x + v.y * b.y + v.z * b.z + v.w * b.w;
#pragma unroll
    for (int o = 16; o > 0; o >>= 1) {
        s1 += __shfl_down_sync(0xffffffffu, s1, o);
        s2 += __shfl_down_sync(0xffffffffu, s2, o);
    }
    if (lane == 0) { ssrc[n * HH + h] = s1; sdst[n * HH + h] = s2; }
}

// ---------------- fused GAT aggregation + bias + LayerNorm + ELU ----------------
// one block (128 thr) per dst node; warp h = head h; lane owns 4 feature dims.
// Online softmax over the node's CSR segment; full output row lives in registers.
__global__ __launch_bounds__(128) void gat_aggregate(
    const int* __restrict__ rowptr, const int* __restrict__ csr,
    const float* __restrict__ ssrc, const float* __restrict__ sdst,
    const float* __restrict__ feat, float* __restrict__ outb,
    const float* __restrict__ bias, const float* __restrict__ g,
    const float* __restrict__ be)
{
    int n = blockIdx.x, t = threadIdx.x;
    int h = t >> 5, lane = t & 31;
    int beg = rowptr[n], end = rowptr[n + 1];

    float sd = sdst[n * HH + h];
    float m = -INFINITY, l = 0.0f;
    float4 acc = make_float4(0.f, 0.f, 0.f, 0.f);
    const float* fb = feat + h * CC + lane * 4;

    int sNext = csr[beg];
#pragma unroll 1
    for (int j = beg; j < end; j++) {
        int s = sNext;
        if (j + 1 < end) sNext = csr[j + 1];
        float e = ssrc[s * HH + h] + sd;
        e = (e > 0.0f) ? e : NEG_SLOPE * e;
        float mn = fmaxf(m, e);
        float sc = __expf(m - mn);
        float p  = __expf(e - mn);
        float4 v = *(const float4*)(fb + (size_t)s * DD);
        acc.x = acc.x * sc + p * v.x;
        acc.y = acc.y * sc + p * v.y;
        acc.z = acc.z * sc + p * v.z;
        acc.w = acc.w * sc + p * v.w;
        l = l * sc + p;
        m = mn;
    }

    float inv = 1.0f / l;
    float4 bb = ((const float4*)bias)[t];
    float4 x;
    x.x = acc.x * inv + bb.x;
    x.y = acc.y * inv + bb.y;
    x.z = acc.z * inv + bb.z;
    x.w = acc.w * inv + bb.w;

    // LayerNorm over the 512-wide row
    __shared__ float sm[4];
    int w = h;
    float s1 = x.x + x.y + x.z + x.w;
#pragma unroll
    for (int o = 16; o > 0; o >>= 1) s1 += __shfl_down_sync(0xffffffffu, s1, o);
    if (lane == 0) sm[w] = s1;
    __syncthreads();
    float mu = (sm[0] + sm[1] + sm[2] + sm[3]) * (1.0f / DD);
    __syncthreads();

    float dx = x.x - mu, dy = x.y - mu, dz = x.z - mu, dw = x.w - mu;
    float ss = dx * dx + dy * dy + dz * dz + dw * dw;
#pragma unroll
    for (int o = 16; o > 0; o >>= 1) ss += __shfl_down_sync(0xffffffffu, ss, o);
    if (lane == 0) sm[w] = ss;
    __syncthreads();
    float var = (sm[0] + sm[1] + sm[2] + sm[3]) * (1.0f / DD);
    float r = rsqrtf(var + LN_EPS);

    float4 gg = ((const float4*)g)[t];
    float4 b2 = ((const float4*)be)[t];
    float4 y;
    y.x = dx * r * gg.x + b2.x;
    y.y = dy * r * gg.y + b2.y;
    y.z = dz * r * gg.z + b2.z;
    y.w = dw * r * gg.w + b2.w;
    y.x = (y.x > 0.f) ? y.x : expm1f(y.x);
    y.y = (y.y > 0.f) ? y.y : expm1f(y.y);
    y.z = (y.z > 0.f) ? y.z : expm1f(y.z);
    y.w = (y.w > 0.f) ? y.w : expm1f(y.w);
    ((float4*)(outb + (size_t)n * DD))[t] = y;
}

// ---------------- final tiny projection ----------------
__global__ void final_proj(const float* __restrict__ z, const float* __restrict__ Wc2,
                           const float* __restrict__ bc2, float* __restrict__ out)
{
    int gw = (blockIdx.x * blockDim.x + threadIdx.x) >> 5;
    int lane = threadIdx.x & 31;
    if (gw >= NN) return;
    const float* zp = z + (size_t)gw * DD;
    float s0 = 0.f, s1 = 0.f;
    for (int k = lane; k < DD; k += 32) {
        float zv = zp[k];
        s0 += zv * Wc2[2 * k];
        s1 += zv * Wc2[2 * k + 1];
    }
#pragma unroll
    for (int o = 16; o > 0; o >>= 1) {
        s0 += __shfl_down_sync(0xffffffffu, s0, o);
        s1 += __shfl_down_sync(0xffffffffu, s1, o);
    }
    if (lane == 0) { out[gw * 2] = s0 + bc2[0]; out[gw * 2 + 1] = s1 + bc2[1]; }
}

// ---------------- host orchestration ----------------
extern "C" void kernel_launch(void* const* d_in, const int* in_sizes, int n_in,
                              void* d_out, int out_size)
{
    const float* x   = (const float*)d_in[0];
    const void*  ei  = d_in[1];
    const float* W1  = (const float*)d_in[2];
    const float* as1 = (const float*)d_in[3];
    const float* ad1 = (const float*)d_in[4];
    const float* b1  = (const float*)d_in[5];
    const float* g1  = (const float*)d_in[6];
    const float* be1 = (const float*)d_in[7];
    const float* W2  = (const float*)d_in[8];
    const float* as2 = (const float*)d_in[9];
    const float* ad2 = (const float*)d_in[10];
    const float* b2  = (const float*)d_in[11];
    const float* g2  = (const float*)d_in[12];
    const float* be2 = (const float*)d_in[13];
    const float* Wc1 = (const float*)d_in[14];
    const float* bc1 = (const float*)d_in[15];
    const float* Wc2 = (const float*)d_in[16];
    const float* bc2 = (const float*)d_in[17];
    float* out = (float*)d_out;

    float *A, *B, *ssrc, *sdst;
    int *rowptr, *cursor, *bsum, *csr;
    cudaGetSymbolAddress((void**)&A,      g_bufA);
    cudaGetSymbolAddress((void**)&B,      g_bufB);
    cudaGetSymbolAddress((void**)&ssrc,   g_ssrc);
    cudaGetSymbolAddress((void**)&sdst,   g_sdst);
    cudaGetSymbolAddress((void**)&rowptr, g_rowptr);
    cudaGetSymbolAddress((void**)&cursor, g_cursor);
    cudaGetSymbolAddress((void**)&bsum,   g_bsum);
    cudaGetSymbolAddress((void**)&csr,    g_csr);

    detect_idx_width<<<1, 256>>>((const unsigned*)ei);

    // CSR build (dst-sorted incidence, self loops included)
    int nb = (NN + 1023) / 1024;
    init_deg<<<(NN + 255) / 256, 256>>>(rowptr);
    count_deg<<<1184, 512>>>(ei, rowptr);
    scan1<<<nb, 1024>>>(rowptr, bsum);
    scan2<<<1, 32>>>(bsum, nb);
    scan3<<<(NN + 255) / 256, 256>>>(rowptr, bsum, cursor);
    fill_csr<<<1184, 512>>>(ei, cursor, csr);

    dim3 gemm_grid(DD / 128, (NN + 127) / 128);

    // layer 1
    gemm128<0><<<gemm_grid, 256>>>(x, W1, A, NN, FIN, DD, nullptr, 0);
    sdot_kernel<<<NN, 128>>>(A, as1, ad1, ssrc, sdst);
    gat_aggregate<<<NN, 128>>>(rowptr, csr, ssrc, sdst, A, B, b1, g1, be1);

    // layer 2
    gemm128<1><<<gemm_grid, 256>>>(B, W2, A, NN, DD, DD, nullptr, 0);
    sdot_kernel<<<NN, 128>>>(A, as2, ad2, ssrc, sdst);
    gat_aggregate<<<NN, 128>>>(rowptr, csr, ssrc, sdst, A, B, b2, g2, be2);

    // classifier
    gemm128<1><<<gemm_grid, 256>>>(B, Wc1, A, NN, DD, DD, bc1, 1);
    final_proj<<<(NN * 32 + 255) / 256, 256>>>(A, Wc2, bc2, out);
}

// round 4
// speedup vs baseline: 2.6767x; 1.5841x over previous
#include <cuda_runtime.h>
#include <math.h>

#define NN   100000
#define EE   1600000
#define ENE  1700000      // E + N self loops
#define HH   4
#define CC   128
#define DD   512
#define FIN  182
#define NEG_SLOPE 0.2f
#define LN_EPS 1e-5f

// ---------------- scratch (device globals) ----------------
__device__ float g_bufA[(size_t)NN * DD];
__device__ float g_bufB[(size_t)NN * DD];
__device__ float g_ssrc[NN * HH];
__device__ float g_sdst[NN * HH];
__device__ int   g_rowptr[NN + 1];
__device__ int   g_cursor[NN];
__device__ int   g_bsum[256];
__device__ int   g_csr[ENE];
__device__ int   g_is64;

// ---------------- edge decode ----------------
__device__ __forceinline__ void load_edge(const void* ei, int ed, int& s, int& d) {
    if (ed >= EE) { s = d = ed - EE; return; }
    if (g_is64) {
        const long long* p = (const long long*)ei;
        s = (int)p[ed]; d = (int)p[EE + ed];
    } else {
        const int* p = (const int*)ei;
        s = p[ed]; d = p[EE + ed];
    }
}

__global__ void detect_idx_width(const unsigned* __restrict__ w) {
    __shared__ unsigned acc[256];
    unsigned v = 0;
    for (int i = threadIdx.x; i < 4096; i += 256)
        if (i & 1) v |= w[i];
    acc[threadIdx.x] = v;
    __syncthreads();
    for (int s = 128; s > 0; s >>= 1) {
        if (threadIdx.x < s) acc[threadIdx.x] |= acc[threadIdx.x + s];
        __syncthreads();
    }
    if (threadIdx.x == 0) g_is64 = (acc[0] == 0u) ? 1 : 0;
}

// ---------------- CSR build ----------------
__global__ void init_deg(int* __restrict__ deg) {
    int i = blockIdx.x * blockDim.x + threadIdx.x;
    if (i < NN) deg[i] = 1;
}

__global__ void count_deg(const void* __restrict__ ei, int* __restrict__ deg) {
    for (int ed = blockIdx.x * blockDim.x + threadIdx.x; ed < EE;
         ed += gridDim.x * blockDim.x) {
        int s, d; load_edge(ei, ed, s, d);
        atomicAdd(&deg[d], 1);
    }
}

__global__ __launch_bounds__(1024) void scan1(int* __restrict__ rp, int* __restrict__ bsum) {
    __shared__ int sh[1024];
    int i = blockIdx.x * 1024 + threadIdx.x;
    int v = (i < NN) ? rp[i] : 0;
    sh[threadIdx.x] = v;
    __syncthreads();
#pragma unroll
    for (int o = 1; o < 1024; o <<= 1) {
        int t = (threadIdx.x >= o) ? sh[threadIdx.x - o] : 0;
        __syncthreads();
        sh[threadIdx.x] += t;
        __syncthreads();
    }
    if (i < NN) rp[i] = sh[threadIdx.x] - v;
    if (threadIdx.x == 1023) bsum[blockIdx.x] = sh[1023];
}

__global__ void scan2(int* __restrict__ bsum, int nb) {
    if (threadIdx.x == 0) {
        int acc = 0;
        for (int i = 0; i < nb; i++) { int t = bsum[i]; bsum[i] = acc; acc += t; }
    }
}

__global__ void scan3(int* __restrict__ rp, const int* __restrict__ bsum,
                      int* __restrict__ cursor) {
    int i = blockIdx.x * blockDim.x + threadIdx.x;
    if (i < NN) {
        int v = rp[i] + bsum[i >> 10];
        rp[i] = v;
        cursor[i] = v;
    }
    if (i == 0) rp[NN] = ENE;
}

__global__ void fill_csr(const void* __restrict__ ei, int* __restrict__ cursor,
                         int* __restrict__ csr) {
    for (int ed = blockIdx.x * blockDim.x + threadIdx.x; ed < ENE;
         ed += gridDim.x * blockDim.x) {
        int s, d; load_edge(ei, ed, s, d);
        int pos = atomicAdd(&cursor[d], 1);
        csr[pos] = s;
    }
}

// ---------------- tf32 tensor-core GEMM ----------------
// C[M,Nc] = A[M,K] @ B[K,Nc] (+bias)(+relu), fp32 in/out, tf32 mma.
// 128x128 block tile, BK=16, 256 threads = 8 warps, warp tile 64x32.
__device__ __forceinline__ unsigned f2tf32(float v) {
    unsigned r;
    asm("cvt.rna.tf32.f32 %0, %1;" : "=r"(r) : "f"(v));
    return r;
}

__device__ __forceinline__ void mma_tf32(float (&c)[4], const unsigned (&a)[4],
                                         const unsigned (&b)[2]) {
    asm volatile(
        "mma.sync.aligned.m16n8k8.row.col.f32.tf32.tf32.f32 "
        "{%0,%1,%2,%3}, {%4,%5,%6,%7}, {%8,%9}, {%0,%1,%2,%3};"
        : "+f"(c[0]), "+f"(c[1]), "+f"(c[2]), "+f"(c[3])
        : "r"(a[0]), "r"(a[1]), "r"(a[2]), "r"(a[3]), "r"(b[0]), "r"(b[1]));
}

#define SPAD 136   // 128 + 8 pad: frag-load addr = 136k+idx -> bank (8k+idx)&31, conflict-free

template <int AVEC>
__global__ __launch_bounds__(256) void gemm_tf32(
    const float* __restrict__ A, const float* __restrict__ B, float* __restrict__ C,
    int M, int K, int Nc, const float* __restrict__ bias, int doRelu)
{
    __shared__ unsigned As[16][SPAD];   // [k][m], tf32 bits
    __shared__ unsigned Bs[16][SPAD];   // [k][n], tf32 bits

    int tid = threadIdx.x;
    int warp = tid >> 5, lane = tid & 31;
    int qr = lane >> 2, qc = lane & 3;
    int m0 = blockIdx.y * 128, n0 = blockIdx.x * 128;
    int wm = (warp >> 2) * 64;          // 0 or 64
    int wn = (warp & 3) * 32;           // 0,32,64,96

    float c[4][4][4];
#pragma unroll
    for (int i = 0; i < 4; i++)
#pragma unroll
        for (int j = 0; j < 4; j++)
#pragma unroll
            for (int k = 0; k < 4; k++) c[i][j][k] = 0.0f;

    // A-load indices: 2 threads per row, each loads 8 consecutive k
    int a_row = tid & 127;
    int a_kk  = (tid >> 7) * 8;         // 0 or 8
    // B-load indices: 16 threads per k-row, each loads 8 consecutive n
    int b_kk  = tid >> 4;               // 0..15
    int b_col = (tid & 15) * 8;

    int kt = (K + 15) / 16;
    for (int t = 0; t < kt; t++) {
        int k0 = t * 16;
        // ---- stage A tile (transposed, tf32-converted) ----
        {
            int gm = m0 + a_row;
            if (AVEC) {
                float4 v0 = make_float4(0.f, 0.f, 0.f, 0.f), v1 = v0;
                if (gm < M) {
                    const float* ap = A + (size_t)gm * K + k0 + a_kk;
                    v0 = *(const float4*)(ap);
                    v1 = *(const float4*)(ap + 4);
                }
                As[a_kk + 0][a_row] = f2tf32(v0.x);
                As[a_kk + 1][a_row] = f2tf32(v0.y);
                As[a_kk + 2][a_row] = f2tf32(v0.z);
                As[a_kk + 3][a_row] = f2tf32(v0.w);
                As[a_kk + 4][a_row] = f2tf32(v1.x);
                As[a_kk + 5][a_row] = f2tf32(v1.y);
                As[a_kk + 6][a_row] = f2tf32(v1.z);
                As[a_kk + 7][a_row] = f2tf32(v1.w);
            } else {
#pragma unroll
                for (int j = 0; j < 8; j++) {
                    int gk = k0 + a_kk + j;
                    float v = 0.0f;
                    if (gm < M && gk < K) v = A[(size_t)gm * K + gk];
                    As[a_kk + j][a_row] = f2tf32(v);
                }
            }
        }
        // ---- stage B tile ----
        {
            float4 v0 = make_float4(0.f, 0.f, 0.f, 0.f), v1 = v0;
            if (k0 + b_kk < K) {
                const float* bp = B + (size_t)(k0 + b_kk) * Nc + n0 + b_col;
                v0 = *(const float4*)(bp);
                v1 = *(const float4*)(bp + 4);
            }
            Bs[b_kk][b_col + 0] = f2tf32(v0.x);
            Bs[b_kk][b_col + 1] = f2tf32(v0.y);
            Bs[b_kk][b_col + 2] = f2tf32(v0.z);
            Bs[b_kk][b_col + 3] = f2tf32(v0.w);
            Bs[b_kk][b_col + 4] = f2tf32(v1.x);
            Bs[b_kk][b_col + 5] = f2tf32(v1.y);
            Bs[b_kk][b_col + 6] = f2tf32(v1.z);
            Bs[b_kk][b_col + 7] = f2tf32(v1.w);
        }
        __syncthreads();

#pragma unroll
        for (int s = 0; s < 2; s++) {
            int k8 = s * 8;
            unsigned a[4][2][2], b[4][2];
#pragma unroll
            for (int mi = 0; mi < 4; mi++) {
                int mb = wm + mi * 16;
                a[mi][0][0] = As[k8 + qc][mb + qr];
                a[mi][0][1] = As[k8 + qc][mb + qr + 8];
                a[mi][1][0] = As[k8 + qc + 4][mb + qr];
                a[mi][1][1] = As[k8 + qc + 4][mb + qr + 8];
            }
#pragma unroll
            for (int nj = 0; nj < 4; nj++) {
                int nb = wn + nj * 8;
                b[nj][0] = Bs[k8 + qc][nb + qr];
                b[nj][1] = Bs[k8 + qc + 4][nb + qr];
            }
#pragma unroll
            for (int mi = 0; mi < 4; mi++) {
                unsigned af[4] = { a[mi][0][0], a[mi][0][1], a[mi][1][0], a[mi][1][1] };
#pragma unroll
                for (int nj = 0; nj < 4; nj++)
                    mma_tf32(c[mi][nj], af, b[nj]);
            }
        }
        __syncthreads();
    }

    // ---- epilogue ----
#pragma unroll
    for (int mi = 0; mi < 4; mi++) {
#pragma unroll
        for (int nj = 0; nj < 4; nj++) {
            int gm0 = m0 + wm + mi * 16 + qr;
            int gn  = n0 + wn + nj * 8 + 2 * qc;
            float2 v0 = make_float2(c[mi][nj][0], c[mi][nj][1]);
            float2 v1 = make_float2(c[mi][nj][2], c[mi][nj][3]);
            if (bias) {
                float bx = bias[gn], by = bias[gn + 1];
                v0.x += bx; v0.y += by; v1.x += bx; v1.y += by;
            }
            if (doRelu) {
                v0.x = fmaxf(v0.x, 0.f); v0.y = fmaxf(v0.y, 0.f);
                v1.x = fmaxf(v1.x, 0.f); v1.y = fmaxf(v1.y, 0.f);
            }
            if (gm0 < M)     *(float2*)(C + (size_t)gm0 * Nc + gn) = v0;
            if (gm0 + 8 < M) *(float2*)(C + (size_t)(gm0 + 8) * Nc + gn) = v1;
        }
    }
}

// ---------------- per-node attention dot products ----------------
__global__ __launch_bounds__(128) void sdot_kernel(
    const float* __restrict__ feat, const float* __restrict__ asrc,
    const float* __restrict__ adst, float* __restrict__ ssrc, float* __restrict__ sdst)
{
    int n = blockIdx.x, t = threadIdx.x;
    int h = t >> 5, lane = t & 31;
    float4 v = ((const float4*)(feat + (size_t)n * DD + h * CC))[lane];
    float4 a = ((const float4*)(asrc + h * CC))[lane];
    float4 b = ((const float4*)(adst + h * CC))[lane];
    float s1 = v.x * a.x + v.y * a.y + v.z * a.z + v.w * a.w;
    float s2 = v.x * b.x + v.y * b.y + v.z * b.z + v.w * b.w;
#pragma unroll
    for (int o = 16; o > 0; o >>= 1) {
        s1 += __shfl_down_sync(0xffffffffu, s1, o);
        s2 += __shfl_down_sync(0xffffffffu, s2, o);
    }
    if (lane == 0) { ssrc[n * HH + h] = s1; sdst[n * HH + h] = s2; }
}

// ---------------- fused GAT aggregation + bias + LayerNorm + ELU ----------------
__global__ __launch_bounds__(128) void gat_aggregate(
    const int* __restrict__ rowptr, const int* __restrict__ csr,
    const float* __restrict__ ssrc, const float* __restrict__ sdst,
    const float* __restrict__ feat, float* __restrict__ outb,
    const float* __restrict__ bias, const float* __restrict__ g,
    const float* __restrict__ be)
{
    int n = blockIdx.x, t = threadIdx.x;
    int h = t >> 5, lane = t & 31;
    int beg = rowptr[n], end = rowptr[n + 1];

    float sd = sdst[n * HH + h];
    float m = -INFINITY, l = 0.0f;
    float4 acc = make_float4(0.f, 0.f, 0.f, 0.f);
    const float* fb = feat + h * CC + lane * 4;

    int sNext = csr[beg];
#pragma unroll 1
    for (int j = beg; j < end; j++) {
        int s = sNext;
        if (j + 1 < end) sNext = csr[j + 1];
        float e = ssrc[s * HH + h] + sd;
        e = (e > 0.0f) ? e : NEG_SLOPE * e;
        float mn = fmaxf(m, e);
        float sc = __expf(m - mn);
        float p  = __expf(e - mn);
        float4 v = *(const float4*)(fb + (size_t)s * DD);
        acc.x = acc.x * sc + p * v.x;
        acc.y = acc.y * sc + p * v.y;
        acc.z = acc.z * sc + p * v.z;
        acc.w = acc.w * sc + p * v.w;
        l = l * sc + p;
        m = mn;
    }

    float inv = 1.0f / l;
    float4 bb = ((const float4*)bias)[t];
    float4 x;
    x.x = acc.x * inv + bb.x;
    x.y = acc.y * inv + bb.y;
    x.z = acc.z * inv + bb.z;
    x.w = acc.w * inv + bb.w;

    __shared__ float sm[4];
    int w = h;
    float s1 = x.x + x.y + x.z + x.w;
#pragma unroll
    for (int o = 16; o > 0; o >>= 1) s1 += __shfl_down_sync(0xffffffffu, s1, o);
    if (lane == 0) sm[w] = s1;
    __syncthreads();
    float mu = (sm[0] + sm[1] + sm[2] + sm[3]) * (1.0f / DD);
    __syncthreads();

    float dx = x.x - mu, dy = x.y - mu, dz = x.z - mu, dw = x.w - mu;
    float ss = dx * dx + dy * dy + dz * dz + dw * dw;
#pragma unroll
    for (int o = 16; o > 0; o >>= 1) ss += __shfl_down_sync(0xffffffffu, ss, o);
    if (lane == 0) sm[w] = ss;
    __syncthreads();
    float var = (sm[0] + sm[1] + sm[2] + sm[3]) * (1.0f / DD);
    float r = rsqrtf(var + LN_EPS);

    float4 gg = ((const float4*)g)[t];
    float4 b2 = ((const float4*)be)[t];
    float4 y;
    y.x = dx * r * gg.x + b2.x;
    y.y = dy * r * gg.y + b2.y;
    y.z = dz * r * gg.z + b2.z;
    y.w = dw * r * gg.w + b2.w;
    y.x = (y.x > 0.f) ? y.x : expm1f(y.x);
    y.y = (y.y > 0.f) ? y.y : expm1f(y.y);
    y.z = (y.z > 0.f) ? y.z : expm1f(y.z);
    y.w = (y.w > 0.f) ? y.w : expm1f(y.w);
    ((float4*)(outb + (size_t)n * DD))[t] = y;
}

// ---------------- final tiny projection ----------------
__global__ void final_proj(const float* __restrict__ z, const float* __restrict__ Wc2,
                           const float* __restrict__ bc2, float* __restrict__ out)
{
    int gw = (blockIdx.x * blockDim.x + threadIdx.x) >> 5;
    int lane = threadIdx.x & 31;
    if (gw >= NN) return;
    const float* zp = z + (size_t)gw * DD;
    float s0 = 0.f, s1 = 0.f;
    for (int k = lane; k < DD; k += 32) {
        float zv = zp[k];
        s0 += zv * Wc2[2 * k];
        s1 += zv * Wc2[2 * k + 1];
    }
#pragma unroll
    for (int o = 16; o > 0; o >>= 1) {
        s0 += __shfl_down_sync(0xffffffffu, s0, o);
        s1 += __shfl_down_sync(0xffffffffu, s1, o);
    }
    if (lane == 0) { out[gw * 2] = s0 + bc2[0]; out[gw * 2 + 1] = s1 + bc2[1]; }
}

// ---------------- host orchestration ----------------
extern "C" void kernel_launch(void* const* d_in, const int* in_sizes, int n_in,
                              void* d_out, int out_size)
{
    const float* x   = (const float*)d_in[0];
    const void*  ei  = d_in[1];
    const float* W1  = (const float*)d_in[2];
    const float* as1 = (const float*)d_in[3];
    const float* ad1 = (const float*)d_in[4];
    const float* b1  = (const float*)d_in[5];
    const float* g1  = (const float*)d_in[6];
    const float* be1 = (const float*)d_in[7];
    const float* W2  = (const float*)d_in[8];
    const float* as2 = (const float*)d_in[9];
    const float* ad2 = (const float*)d_in[10];
    const float* b2  = (const float*)d_in[11];
    const float* g2  = (const float*)d_in[12];
    const float* be2 = (const float*)d_in[13];
    const float* Wc1 = (const float*)d_in[14];
    const float* bc1 = (const float*)d_in[15];
    const float* Wc2 = (const float*)d_in[16];
    const float* bc2 = (const float*)d_in[17];
    float* out = (float*)d_out;

    float *A, *B, *ssrc, *sdst;
    int *rowptr, *cursor, *bsum, *csr;
    cudaGetSymbolAddress((void**)&A,      g_bufA);
    cudaGetSymbolAddress((void**)&B,      g_bufB);
    cudaGetSymbolAddress((void**)&ssrc,   g_ssrc);
    cudaGetSymbolAddress((void**)&sdst,   g_sdst);
    cudaGetSymbolAddress((void**)&rowptr, g_rowptr);
    cudaGetSymbolAddress((void**)&cursor, g_cursor);
    cudaGetSymbolAddress((void**)&bsum,   g_bsum);
    cudaGetSymbolAddress((void**)&csr,    g_csr);

    detect_idx_width<<<1, 256>>>((const unsigned*)ei);

    // CSR build
    int nb = (NN + 1023) / 1024;
    init_deg<<<(NN + 255) / 256, 256>>>(rowptr);
    count_deg<<<1184, 512>>>(ei, rowptr);
    scan1<<<nb, 1024>>>(rowptr, bsum);
    scan2<<<1, 32>>>(bsum, nb);
    scan3<<<(NN + 255) / 256, 256>>>(rowptr, bsum, cursor);
    fill_csr<<<1184, 512>>>(ei, cursor, csr);

    dim3 gemm_grid(DD / 128, (NN + 127) / 128);

    // layer 1
    gemm_tf32<0><<<gemm_grid, 256>>>(x, W1, A, NN, FIN, DD, nullptr, 0);
    sdot_kernel<<<NN, 128>>>(A, as1, ad1, ssrc, sdst);
    gat_aggregate<<<NN, 128>>>(rowptr, csr, ssrc, sdst, A, B, b1, g1, be1);

    // layer 2
    gemm_tf32<1><<<gemm_grid, 256>>>(B, W2, A, NN, DD, DD, nullptr, 0);
    sdot_kernel<<<NN, 128>>>(A, as2, ad2, ssrc, sdst);
    gat_aggregate<<<NN, 128>>>(rowptr, csr, ssrc, sdst, A, B, b2, g2, be2);

    // classifier
    gemm_tf32<1><<<gemm_grid, 256>>>(B, Wc1, A, NN, DD, DD, bc1, 1);
    final_proj<<<(NN * 32 + 255) / 256, 256>>>(A, Wc2, bc2, out);
}

// round 5
// speedup vs baseline: 2.7555x; 1.0295x over previous
#include <cuda_runtime.h>
#include <math.h>

#define NN   100000
#define EE   1600000
#define ENE  1700000      // E + N self loops
#define HH   4
#define CC   128
#define DD   512
#define FIN  182
#define NEG_SLOPE 0.2f
#define LN_EPS 1e-5f

// ---------------- scratch (device globals) ----------------
__device__ float g_bufA[(size_t)NN * DD];
__device__ float g_bufB[(size_t)NN * DD];
__device__ float g_ssrc[NN * HH];
__device__ float g_sdst[NN * HH];
__device__ int   g_rowptr[NN + 1];
__device__ int   g_cursor[NN];
__device__ int   g_bsum[256];
__device__ int   g_csr[ENE];
__device__ int   g_is64;

// ---------------- edge decode ----------------
__device__ __forceinline__ void load_edge(const void* ei, int ed, int& s, int& d) {
    if (ed >= EE) { s = d = ed - EE; return; }
    if (g_is64) {
        const long long* p = (const long long*)ei;
        s = (int)p[ed]; d = (int)p[EE + ed];
    } else {
        const int* p = (const int*)ei;
        s = p[ed]; d = p[EE + ed];
    }
}

__global__ void detect_idx_width(const unsigned* __restrict__ w) {
    __shared__ unsigned acc[256];
    unsigned v = 0;
    for (int i = threadIdx.x; i < 4096; i += 256)
        if (i & 1) v |= w[i];
    acc[threadIdx.x] = v;
    __syncthreads();
    for (int s = 128; s > 0; s >>= 1) {
        if (threadIdx.x < s) acc[threadIdx.x] |= acc[threadIdx.x + s];
        __syncthreads();
    }
    if (threadIdx.x == 0) g_is64 = (acc[0] == 0u) ? 1 : 0;
}

// ---------------- CSR build ----------------
__global__ void init_deg(int* __restrict__ deg) {
    int i = blockIdx.x * blockDim.x + threadIdx.x;
    if (i < NN) deg[i] = 1;
}

__global__ void count_deg(const void* __restrict__ ei, int* __restrict__ deg) {
    for (int ed = blockIdx.x * blockDim.x + threadIdx.x; ed < EE;
         ed += gridDim.x * blockDim.x) {
        int s, d; load_edge(ei, ed, s, d);
        atomicAdd(&deg[d], 1);
    }
}

__global__ __launch_bounds__(1024) void scan1(int* __restrict__ rp, int* __restrict__ bsum) {
    __shared__ int sh[1024];
    int i = blockIdx.x * 1024 + threadIdx.x;
    int v = (i < NN) ? rp[i] : 0;
    sh[threadIdx.x] = v;
    __syncthreads();
#pragma unroll
    for (int o = 1; o < 1024; o <<= 1) {
        int t = (threadIdx.x >= o) ? sh[threadIdx.x - o] : 0;
        __syncthreads();
        sh[threadIdx.x] += t;
        __syncthreads();
    }
    if (i < NN) rp[i] = sh[threadIdx.x] - v;
    if (threadIdx.x == 1023) bsum[blockIdx.x] = sh[1023];
}

__global__ void scan2(int* __restrict__ bsum, int nb) {
    if (threadIdx.x == 0) {
        int acc = 0;
        for (int i = 0; i < nb; i++) { int t = bsum[i]; bsum[i] = acc; acc += t; }
    }
}

__global__ void scan3(int* __restrict__ rp, const int* __restrict__ bsum,
                      int* __restrict__ cursor) {
    int i = blockIdx.x * blockDim.x + threadIdx.x;
    if (i < NN) {
        int v = rp[i] + bsum[i >> 10];
        rp[i] = v;
        cursor[i] = v;
    }
    if (i == 0) rp[NN] = ENE;
}

__global__ void fill_csr(const void* __restrict__ ei, int* __restrict__ cursor,
                         int* __restrict__ csr) {
    for (int ed = blockIdx.x * blockDim.x + threadIdx.x; ed < ENE;
         ed += gridDim.x * blockDim.x) {
        int s, d; load_edge(ei, ed, s, d);
        int pos = atomicAdd(&cursor[d], 1);
        csr[pos] = s;
    }
}

// ---------------- tf32 tensor-core GEMM (pipelined, optional fused sdot) ----
__device__ __forceinline__ unsigned f2tf32(float v) {
    unsigned r;
    asm("cvt.rna.tf32.f32 %0, %1;" : "=r"(r) : "f"(v));
    return r;
}

__device__ __forceinline__ void mma_tf32(float (&c)[4], const unsigned (&a)[4],
                                         const unsigned (&b)[2]) {
    asm volatile(
        "mma.sync.aligned.m16n8k8.row.col.f32.tf32.tf32.f32 "
        "{%0,%1,%2,%3}, {%4,%5,%6,%7}, {%8,%9}, {%0,%1,%2,%3};"
        : "+f"(c[0]), "+f"(c[1]), "+f"(c[2]), "+f"(c[3])
        : "r"(a[0]), "r"(a[1]), "r"(a[2]), "r"(a[3]), "r"(b[0]), "r"(b[1]));
}

#define SPAD 136   // 128 + 8 pad: frag load bank (8k+idx)&31, conflict-free

// C[M,Nc]=A[M,K]@B[K,Nc] (+bias)(+relu). 128x128 tile, BK=16, 256 thr, 8 warps 64x32.
// 2-stage register-staged pipeline. SDOT: also emit ssrc/sdst (head = blockIdx.x).
template <int AVEC, int SDOT>
__global__ __launch_bounds__(256) void gemm_tf32(
    const float* __restrict__ A, const float* __restrict__ B, float* __restrict__ C,
    int M, int K, int Nc, const float* __restrict__ bias, int doRelu,
    const float* __restrict__ asrc, const float* __restrict__ adst,
    float* __restrict__ ssrc, float* __restrict__ sdst)
{
    __shared__ unsigned As[2][16][SPAD];
    __shared__ unsigned Bs[2][16][SPAD];
    __shared__ float red_s[128], red_d[128];

    int tid = threadIdx.x;
    int warp = tid >> 5, lane = tid & 31;
    int qr = lane >> 2, qc = lane & 3;
    int m0 = blockIdx.y * 128, n0 = blockIdx.x * 128;
    int wm = (warp >> 2) * 64;
    int wn = (warp & 3) * 32;

    float c[4][4][4];
#pragma unroll
    for (int i = 0; i < 4; i++)
#pragma unroll
        for (int j = 0; j < 4; j++)
#pragma unroll
            for (int k = 0; k < 4; k++) c[i][j][k] = 0.0f;

    if (SDOT && tid < 128) { red_s[tid] = 0.0f; red_d[tid] = 0.0f; }

    int a_row = tid & 127;
    int a_kk  = (tid >> 7) * 8;       // 0 or 8
    int b_kk  = tid >> 4;             // 0..15
    int b_col = (tid & 15) * 8;

    float a_st[8], b_st[8];
    int kt = (K + 15) / 16;

    // ---- staged load: global -> regs ----
    auto stage_load = [&](int t) {
        int k0 = t * 16;
        int gm = m0 + a_row;
        if (AVEC) {
            if (gm < M) {
                const float* ap = A + (size_t)gm * K + k0 + a_kk;
                float4 v0 = *(const float4*)(ap);
                float4 v1 = *(const float4*)(ap + 4);
                a_st[0] = v0.x; a_st[1] = v0.y; a_st[2] = v0.z; a_st[3] = v0.w;
                a_st[4] = v1.x; a_st[5] = v1.y; a_st[6] = v1.z; a_st[7] = v1.w;
            } else {
#pragma unroll
                for (int j = 0; j < 8; j++) a_st[j] = 0.0f;
            }
        } else {
#pragma unroll
            for (int j = 0; j < 8; j++) {
                int gk = k0 + a_kk + j;
                a_st[j] = (gm < M && gk < K) ? A[(size_t)gm * K + gk] : 0.0f;
            }
        }
        if (k0 + b_kk < K) {
            const float* bp = B + (size_t)(k0 + b_kk) * Nc + n0 + b_col;
            float4 v0 = *(const float4*)(bp);
            float4 v1 = *(const float4*)(bp + 4);
            b_st[0] = v0.x; b_st[1] = v0.y; b_st[2] = v0.z; b_st[3] = v0.w;
            b_st[4] = v1.x; b_st[5] = v1.y; b_st[6] = v1.z; b_st[7] = v1.w;
        } else {
#pragma unroll
            for (int j = 0; j < 8; j++) b_st[j] = 0.0f;
        }
    };
    // ---- staged store: regs -> smem (tf32 convert) ----
    auto stage_store = [&](int buf) {
#pragma unroll
        for (int j = 0; j < 8; j++) As[buf][a_kk + j][a_row] = f2tf32(a_st[j]);
#pragma unroll
        for (int j = 0; j < 8; j++) Bs[buf][b_kk][b_col + j] = f2tf32(b_st[j]);
    };

    stage_load(0);
    stage_store(0);
    __syncthreads();

    for (int t = 0; t < kt; t++) {
        int cur = t & 1;
        if (t + 1 < kt) stage_load(t + 1);

#pragma unroll
        for (int s = 0; s < 2; s++) {
            int k8 = s * 8;
            unsigned b[4][2];
#pragma unroll
            for (int nj = 0; nj < 4; nj++) {
                int nb = wn + nj * 8;
                b[nj][0] = Bs[cur][k8 + qc][nb + qr];
                b[nj][1] = Bs[cur][k8 + qc + 4][nb + qr];
            }
#pragma unroll
            for (int mi = 0; mi < 4; mi++) {
                int mb = wm + mi * 16;
                unsigned af[4];
                af[0] = As[cur][k8 + qc][mb + qr];
                af[1] = As[cur][k8 + qc][mb + qr + 8];
                af[2] = As[cur][k8 + qc + 4][mb + qr];
                af[3] = As[cur][k8 + qc + 4][mb + qr + 8];
#pragma unroll
                for (int nj = 0; nj < 4; nj++)
                    mma_tf32(c[mi][nj], af, b[nj]);
            }
        }

        if (t + 1 < kt) stage_store((t + 1) & 1);
        __syncthreads();
    }

    // ---- epilogue: store C (+bias/relu); optionally fused attention dots ----
    const float* ap = SDOT ? (asrc + blockIdx.x * CC) : nullptr;
    const float* dp = SDOT ? (adst + blockIdx.x * CC) : nullptr;

#pragma unroll
    for (int mi = 0; mi < 4; mi++) {
        float s0s = 0.f, s0d = 0.f, s1s = 0.f, s1d = 0.f;
#pragma unroll
        for (int nj = 0; nj < 4; nj++) {
            int gm0 = m0 + wm + mi * 16 + qr;
            int col = wn + nj * 8 + 2 * qc;
            int gn  = n0 + col;
            float2 v0 = make_float2(c[mi][nj][0], c[mi][nj][1]);
            float2 v1 = make_float2(c[mi][nj][2], c[mi][nj][3]);
            if (bias) {
                float bx = bias[gn], by = bias[gn + 1];
                v0.x += bx; v0.y += by; v1.x += bx; v1.y += by;
            }
            if (doRelu) {
                v0.x = fmaxf(v0.x, 0.f); v0.y = fmaxf(v0.y, 0.f);
                v1.x = fmaxf(v1.x, 0.f); v1.y = fmaxf(v1.y, 0.f);
            }
            if (gm0 < M)     *(float2*)(C + (size_t)gm0 * Nc + gn) = v0;
            if (gm0 + 8 < M) *(float2*)(C + (size_t)(gm0 + 8) * Nc + gn) = v1;
            if (SDOT) {
                float a0 = ap[col], a1 = ap[col + 1];
                float d0 = dp[col], d1 = dp[col + 1];
                s0s += v0.x * a0 + v0.y * a1;
                s0d += v0.x * d0 + v0.y * d1;
                s1s += v1.x * a0 + v1.y * a1;
                s1d += v1.x * d0 + v1.y * d1;
            }
        }
        if (SDOT) {
            // reduce over the qc quad (lanes differing in bits 0-1)
#pragma unroll
            for (int o = 1; o <= 2; o <<= 1) {
                s0s += __shfl_xor_sync(0xffffffffu, s0s, o);
                s0d += __shfl_xor_sync(0xffffffffu, s0d, o);
                s1s += __shfl_xor_sync(0xffffffffu, s1s, o);
                s1d += __shfl_xor_sync(0xffffffffu, s1d, o);
            }
            if (qc == 0) {
                int r0 = wm + mi * 16 + qr;
                atomicAdd(&red_s[r0], s0s);
                atomicAdd(&red_d[r0], s0d);
                atomicAdd(&red_s[r0 + 8], s1s);
                atomicAdd(&red_d[r0 + 8], s1d);
            }
        }
    }

    if (SDOT) {
        __syncthreads();
        if (tid < 128) {
            int gm = m0 + tid;
            if (gm < M) {
                ssrc[gm * HH + blockIdx.x] = red_s[tid];
                sdst[gm * HH + blockIdx.x] = red_d[tid];
            }
        }
    }
}

// ---------------- fused GAT aggregation + bias + LayerNorm + ELU ----------------
__global__ __launch_bounds__(128) void gat_aggregate(
    const int* __restrict__ rowptr, const int* __restrict__ csr,
    const float* __restrict__ ssrc, const float* __restrict__ sdst,
    const float* __restrict__ feat, float* __restrict__ outb,
    const float* __restrict__ bias, const float* __restrict__ g,
    const float* __restrict__ be)
{
    int n = blockIdx.x, t = threadIdx.x;
    int h = t >> 5, lane = t & 31;
    int beg = rowptr[n], end = rowptr[n + 1];

    float sd = sdst[n * HH + h];
    float m = -INFINITY, l = 0.0f;
    float4 acc = make_float4(0.f, 0.f, 0.f, 0.f);
    const float* fb = feat + h * CC + lane * 4;

    int sNext = csr[beg];
#pragma unroll 1
    for (int j = beg; j < end; j++) {
        int s = sNext;
        if (j + 1 < end) sNext = csr[j + 1];
        float e = ssrc[s * HH + h] + sd;
        e = (e > 0.0f) ? e : NEG_SLOPE * e;
        float mn = fmaxf(m, e);
        float sc = __expf(m - mn);
        float p  = __expf(e - mn);
        float4 v = *(const float4*)(fb + (size_t)s * DD);
        acc.x = acc.x * sc + p * v.x;
        acc.y = acc.y * sc + p * v.y;
        acc.z = acc.z * sc + p * v.z;
        acc.w = acc.w * sc + p * v.w;
        l = l * sc + p;
        m = mn;
    }

    float inv = 1.0f / l;
    float4 bb = ((const float4*)bias)[t];
    float4 x;
    x.x = acc.x * inv + bb.x;
    x.y = acc.y * inv + bb.y;
    x.z = acc.z * inv + bb.z;
    x.w = acc.w * inv + bb.w;

    __shared__ float sm[4];
    float s1 = x.x + x.y + x.z + x.w;
#pragma unroll
    for (int o = 16; o > 0; o >>= 1) s1 += __shfl_down_sync(0xffffffffu, s1, o);
    if (lane == 0) sm[h] = s1;
    __syncthreads();
    float mu = (sm[0] + sm[1] + sm[2] + sm[3]) * (1.0f / DD);
    __syncthreads();

    float dx = x.x - mu, dy = x.y - mu, dz = x.z - mu, dw = x.w - mu;
    float ss = dx * dx + dy * dy + dz * dz + dw * dw;
#pragma unroll
    for (int o = 16; o > 0; o >>= 1) ss += __shfl_down_sync(0xffffffffu, ss, o);
    if (lane == 0) sm[h] = ss;
    __syncthreads();
    float var = (sm[0] + sm[1] + sm[2] + sm[3]) * (1.0f / DD);
    float r = rsqrtf(var + LN_EPS);

    float4 gg = ((const float4*)g)[t];
    float4 b2 = ((const float4*)be)[t];
    float4 y;
    y.x = dx * r * gg.x + b2.x;
    y.y = dy * r * gg.y + b2.y;
    y.z = dz * r * gg.z + b2.z;
    y.w = dw * r * gg.w + b2.w;
    y.x = (y.x > 0.f) ? y.x : expm1f(y.x);
    y.y = (y.y > 0.f) ? y.y : expm1f(y.y);
    y.z = (y.z > 0.f) ? y.z : expm1f(y.z);
    y.w = (y.w > 0.f) ? y.w : expm1f(y.w);
    ((float4*)(outb + (size_t)n * DD))[t] = y;
}

// ---------------- final tiny projection ----------------
__global__ void final_proj(const float* __restrict__ z, const float* __restrict__ Wc2,
                           const float* __restrict__ bc2, float* __restrict__ out)
{
    int gw = (blockIdx.x * blockDim.x + threadIdx.x) >> 5;
    int lane = threadIdx.x & 31;
    if (gw >= NN) return;
    const float* zp = z + (size_t)gw * DD;
    float s0 = 0.f, s1 = 0.f;
    for (int k = lane; k < DD; k += 32) {
        float zv = zp[k];
        s0 += zv * Wc2[2 * k];
        s1 += zv * Wc2[2 * k + 1];
    }
#pragma unroll
    for (int o = 16; o > 0; o >>= 1) {
        s0 += __shfl_down_sync(0xffffffffu, s0, o);
        s1 += __shfl_down_sync(0xffffffffu, s1, o);
    }
    if (lane == 0) { out[gw * 2] = s0 + bc2[0]; out[gw * 2 + 1] = s1 + bc2[1]; }
}

// ---------------- host orchestration ----------------
extern "C" void kernel_launch(void* const* d_in, const int* in_sizes, int n_in,
                              void* d_out, int out_size)
{
    const float* x   = (const float*)d_in[0];
    const void*  ei  = d_in[1];
    const float* W1  = (const float*)d_in[2];
    const float* as1 = (const float*)d_in[3];
    const float* ad1 = (const float*)d_in[4];
    const float* b1  = (const float*)d_in[5];
    const float* g1  = (const float*)d_in[6];
    const float* be1 = (const float*)d_in[7];
    const float* W2  = (const float*)d_in[8];
    const float* as2 = (const float*)d_in[9];
    const float* ad2 = (const float*)d_in[10];
    const float* b2  = (const float*)d_in[11];
    const float* g2  = (const float*)d_in[12];
    const float* be2 = (const float*)d_in[13];
    const float* Wc1 = (const float*)d_in[14];
    const float* bc1 = (const float*)d_in[15];
    const float* Wc2 = (const float*)d_in[16];
    const float* bc2 = (const float*)d_in[17];
    float* out = (float*)d_out;

    float *A, *B, *ssrc, *sdst;
    int *rowptr, *cursor, *bsum, *csr;
    cudaGetSymbolAddress((void**)&A,      g_bufA);
    cudaGetSymbolAddress((void**)&B,      g_bufB);
    cudaGetSymbolAddress((void**)&ssrc,   g_ssrc);
    cudaGetSymbolAddress((void**)&sdst,   g_sdst);
    cudaGetSymbolAddress((void**)&rowptr, g_rowptr);
    cudaGetSymbolAddress((void**)&cursor, g_cursor);
    cudaGetSymbolAddress((void**)&bsum,   g_bsum);
    cudaGetSymbolAddress((void**)&csr,    g_csr);

    detect_idx_width<<<1, 256>>>((const unsigned*)ei);

    // CSR build
    int nb = (NN + 1023) / 1024;
    init_deg<<<(NN + 255) / 256, 256>>>(rowptr);
    count_deg<<<1184, 512>>>(ei, rowptr);
    scan1<<<nb, 1024>>>(rowptr, bsum);
    scan2<<<1, 32>>>(bsum, nb);
    scan3<<<(NN + 255) / 256, 256>>>(rowptr, bsum, cursor);
    fill_csr<<<1184, 512>>>(ei, cursor, csr);

    dim3 gemm_grid(DD / 128, (NN + 127) / 128);

    // layer 1: GEMM + fused attention dots
    gemm_tf32<0, 1><<<gemm_grid, 256>>>(x, W1, A, NN, FIN, DD, nullptr, 0,
                                        as1, ad1, ssrc, sdst);
    gat_aggregate<<<NN, 128>>>(rowptr, csr, ssrc, sdst, A, B, b1, g1, be1);

    // layer 2
    gemm_tf32<1, 1><<<gemm_grid, 256>>>(B, W2, A, NN, DD, DD, nullptr, 0,
                                        as2, ad2, ssrc, sdst);
    gat_aggregate<<<NN, 128>>>(rowptr, csr, ssrc, sdst, A, B, b2, g2, be2);

    // classifier
    gemm_tf32<1, 0><<<gemm_grid, 256>>>(B, Wc1, A, NN, DD, DD, bc1, 1,
                                        nullptr, nullptr, nullptr, nullptr);
    final_proj<<<(NN * 32 + 255) / 256, 256>>>(A, Wc2, bc2, out);
}

// round 8
// speedup vs baseline: 2.8895x; 1.0486x over previous
#include <cuda_runtime.h>
#include <cuda_fp16.h>
#include <math.h>

#define NN   100000
#define EE   1600000
#define ENE  1700000      // E + N self loops
#define HH   4
#define CC   128
#define DD   512
#define FIN  182
#define NEG_SLOPE 0.2f
#define LN_EPS 1e-5f

// ---------------- scratch (device globals) ----------------
__device__ float  g_bufA[(size_t)NN * DD];    // fp32 (z / classifier input)
__device__ float  g_bufB[(size_t)NN * DD];    // fp32 (LN'd features f1/f2)
__device__ __half g_half[(size_t)NN * DD];    // fp16 gather features (h1/h2)
__device__ float  g_ssrc[NN * HH];
__device__ float  g_sdst[NN * HH];
__device__ int    g_rowptr[NN + 1];
__device__ int    g_cursor[NN];
__device__ int    g_bsum[256];
__device__ int    g_csr[ENE];
__device__ int    g_is64;

// ---------------- edge decode ----------------
__device__ __forceinline__ void load_edge(const void* ei, int ed, int& s, int& d) {
    if (ed >= EE) { s = d = ed - EE; return; }
    if (g_is64) {
        const long long* p = (const long long*)ei;
        s = (int)p[ed]; d = (int)p[EE + ed];
    } else {
        const int* p = (const int*)ei;
        s = p[ed]; d = p[EE + ed];
    }
}

__global__ void detect_idx_width(const unsigned* __restrict__ w) {
    __shared__ unsigned acc[256];
    unsigned v = 0;
    for (int i = threadIdx.x; i < 4096; i += 256)
        if (i & 1) v |= w[i];
    acc[threadIdx.x] = v;
    __syncthreads();
    for (int s = 128; s > 0; s >>= 1) {
        if (threadIdx.x < s) acc[threadIdx.x] |= acc[threadIdx.x + s];
        __syncthreads();
    }
    if (threadIdx.x == 0) g_is64 = (acc[0] == 0u) ? 1 : 0;
}

// ---------------- CSR build ----------------
__global__ void init_deg(int* __restrict__ deg) {
    int i = blockIdx.x * blockDim.x + threadIdx.x;
    if (i < NN) deg[i] = 1;
}

__global__ void count_deg(const void* __restrict__ ei, int* __restrict__ deg) {
    for (int ed = blockIdx.x * blockDim.x + threadIdx.x; ed < EE;
         ed += gridDim.x * blockDim.x) {
        int s, d; load_edge(ei, ed, s, d);
        atomicAdd(&deg[d], 1);
    }
}

__global__ __launch_bounds__(1024) void scan1(int* __restrict__ rp, int* __restrict__ bsum) {
    __shared__ int sh[1024];
    int i = blockIdx.x * 1024 + threadIdx.x;
    int v = (i < NN) ? rp[i] : 0;
    sh[threadIdx.x] = v;
    __syncthreads();
#pragma unroll
    for (int o = 1; o < 1024; o <<= 1) {
        int t = (threadIdx.x >= o) ? sh[threadIdx.x - o] : 0;
        __syncthreads();
        sh[threadIdx.x] += t;
        __syncthreads();
    }
    if (i < NN) rp[i] = sh[threadIdx.x] - v;
    if (threadIdx.x == 1023) bsum[blockIdx.x] = sh[1023];
}

__global__ void scan2(int* __restrict__ bsum, int nb) {
    if (threadIdx.x == 0) {
        int acc = 0;
        for (int i = 0; i < nb; i++) { int t = bsum[i]; bsum[i] = acc; acc += t; }
    }
}

__global__ void scan3(int* __restrict__ rp, const int* __restrict__ bsum,
                      int* __restrict__ cursor) {
    int i = blockIdx.x * blockDim.x + threadIdx.x;
    if (i < NN) {
        int v = rp[i] + bsum[i >> 10];
        rp[i] = v;
        cursor[i] = v;
    }
    if (i == 0) rp[NN] = ENE;
}

__global__ void fill_csr(const void* __restrict__ ei, int* __restrict__ cursor,
                         int* __restrict__ csr) {
    for (int ed = blockIdx.x * blockDim.x + threadIdx.x; ed < ENE;
         ed += gridDim.x * blockDim.x) {
        int s, d; load_edge(ei, ed, s, d);
        int pos = atomicAdd(&cursor[d], 1);
        csr[pos] = s;
    }
}

// ---------------- tf32 tensor-core GEMM (pipelined, fused sdot, half out) ----
__device__ __forceinline__ unsigned f2tf32(float v) {
    unsigned r;
    asm("cvt.rna.tf32.f32 %0, %1;" : "=r"(r) : "f"(v));
    return r;
}

__device__ __forceinline__ void mma_tf32(float (&c)[4], const unsigned (&a)[4],
                                         const unsigned (&b)[2]) {
    asm volatile(
        "mma.sync.aligned.m16n8k8.row.col.f32.tf32.tf32.f32 "
        "{%0,%1,%2,%3}, {%4,%5,%6,%7}, {%8,%9}, {%0,%1,%2,%3};"
        : "+f"(c[0]), "+f"(c[1]), "+f"(c[2]), "+f"(c[3])
        : "r"(a[0]), "r"(a[1]), "r"(a[2]), "r"(a[3]), "r"(b[0]), "r"(b[1]));
}

#define SPAD 136   // 128 + 8 pad: frag load bank (8k+idx)&31, conflict-free

// 128x128 tile, BK=16, 256 thr, 8 warps of 64x32, 2-stage register pipeline.
// OUTH: write C as fp16 (Ch). SDOT: emit ssrc/sdst (head = blockIdx.x).
template <int AVEC, int SDOT, int OUTH>
__global__ __launch_bounds__(256) void gemm_tf32(
    const float* __restrict__ A, const float* __restrict__ B, float* __restrict__ C,
    __half* __restrict__ Ch,
    int M, int K, int Nc, const float* __restrict__ bias, int doRelu,
    const float* __restrict__ asrc, const float* __restrict__ adst,
    float* __restrict__ ssrc, float* __restrict__ sdst)
{
    __shared__ unsigned As[2][16][SPAD];
    __shared__ unsigned Bs[2][16][SPAD];
    __shared__ float red_s[128], red_d[128];

    int tid = threadIdx.x;
    int warp = tid >> 5, lane = tid & 31;
    int qr = lane >> 2, qc = lane & 3;
    int m0 = blockIdx.y * 128, n0 = blockIdx.x * 128;
    int wm = (warp >> 2) * 64;
    int wn = (warp & 3) * 32;

    float c[4][4][4];
#pragma unroll
    for (int i = 0; i < 4; i++)
#pragma unroll
        for (int j = 0; j < 4; j++)
#pragma unroll
            for (int k = 0; k < 4; k++) c[i][j][k] = 0.0f;

    if (SDOT && tid < 128) { red_s[tid] = 0.0f; red_d[tid] = 0.0f; }

    int a_row = tid & 127;
    int a_kk  = (tid >> 7) * 8;
    int b_kk  = tid >> 4;
    int b_col = (tid & 15) * 8;

    float a_st[8], b_st[8];
    int kt = (K + 15) / 16;

    auto stage_load = [&](int t) {
        int k0 = t * 16;
        int gm = m0 + a_row;
        if (AVEC) {
            if (gm < M) {
                const float* ap = A + (size_t)gm * K + k0 + a_kk;
                float4 v0 = *(const float4*)(ap);
                float4 v1 = *(const float4*)(ap + 4);
                a_st[0] = v0.x; a_st[1] = v0.y; a_st[2] = v0.z; a_st[3] = v0.w;
                a_st[4] = v1.x; a_st[5] = v1.y; a_st[6] = v1.z; a_st[7] = v1.w;
            } else {
#pragma unroll
                for (int j = 0; j < 8; j++) a_st[j] = 0.0f;
            }
        } else {
#pragma unroll
            for (int j = 0; j < 8; j++) {
                int gk = k0 + a_kk + j;
                a_st[j] = (gm < M && gk < K) ? A[(size_t)gm * K + gk] : 0.0f;
            }
        }
        if (k0 + b_kk < K) {
            const float* bp = B + (size_t)(k0 + b_kk) * Nc + n0 + b_col;
            float4 v0 = *(const float4*)(bp);
            float4 v1 = *(const float4*)(bp + 4);
            b_st[0] = v0.x; b_st[1] = v0.y; b_st[2] = v0.z; b_st[3] = v0.w;
            b_st[4] = v1.x; b_st[5] = v1.y; b_st[6] = v1.z; b_st[7] = v1.w;
        } else {
#pragma unroll
            for (int j = 0; j < 8; j++) b_st[j] = 0.0f;
        }
    };
    auto stage_store = [&](int buf) {
#pragma unroll
        for (int j = 0; j < 8; j++) As[buf][a_kk + j][a_row] = f2tf32(a_st[j]);
#pragma unroll
        for (int j = 0; j < 8; j++) Bs[buf][b_kk][b_col + j] = f2tf32(b_st[j]);
    };

    stage_load(0);
    stage_store(0);
    __syncthreads();

    for (int t = 0; t < kt; t++) {
        int cur = t & 1;
        if (t + 1 < kt) stage_load(t + 1);

#pragma unroll
        for (int s = 0; s < 2; s++) {
            int k8 = s * 8;
            unsigned b[4][2];
#pragma unroll
            for (int nj = 0; nj < 4; nj++) {
                int nb = wn + nj * 8;
                b[nj][0] = Bs[cur][k8 + qc][nb + qr];
                b[nj][1] = Bs[cur][k8 + qc + 4][nb + qr];
            }
#pragma unroll
            for (int mi = 0; mi < 4; mi++) {
                int mb = wm + mi * 16;
                unsigned af[4];
                af[0] = As[cur][k8 + qc][mb + qr];
                af[1] = As[cur][k8 + qc][mb + qr + 8];
                af[2] = As[cur][k8 + qc + 4][mb + qr];
                af[3] = As[cur][k8 + qc + 4][mb + qr + 8];
#pragma unroll
                for (int nj = 0; nj < 4; nj++)
                    mma_tf32(c[mi][nj], af, b[nj]);
            }
        }

        if (t + 1 < kt) stage_store((t + 1) & 1);
        __syncthreads();
    }

    // ---- epilogue ----
    const float* ap = SDOT ? (asrc + blockIdx.x * CC) : nullptr;
    const float* dp = SDOT ? (adst + blockIdx.x * CC) : nullptr;

#pragma unroll
    for (int mi = 0; mi < 4; mi++) {
        float s0s = 0.f, s0d = 0.f, s1s = 0.f, s1d = 0.f;
#pragma unroll
        for (int nj = 0; nj < 4; nj++) {
            int gm0 = m0 + wm + mi * 16 + qr;
            int col = wn + nj * 8 + 2 * qc;
            int gn  = n0 + col;
            float2 v0 = make_float2(c[mi][nj][0], c[mi][nj][1]);
            float2 v1 = make_float2(c[mi][nj][2], c[mi][nj][3]);
            if (bias) {
                float bx = bias[gn], by = bias[gn + 1];
                v0.x += bx; v0.y += by; v1.x += bx; v1.y += by;
            }
            if (doRelu) {
                v0.x = fmaxf(v0.x, 0.f); v0.y = fmaxf(v0.y, 0.f);
                v1.x = fmaxf(v1.x, 0.f); v1.y = fmaxf(v1.y, 0.f);
            }
            if (OUTH) {
                if (gm0 < M)
                    *(__half2*)(Ch + (size_t)gm0 * Nc + gn) = __floats2half2_rn(v0.x, v0.y);
                if (gm0 + 8 < M)
                    *(__half2*)(Ch + (size_t)(gm0 + 8) * Nc + gn) = __floats2half2_rn(v1.x, v1.y);
            } else {
                if (gm0 < M)     *(float2*)(C + (size_t)gm0 * Nc + gn) = v0;
                if (gm0 + 8 < M) *(float2*)(C + (size_t)(gm0 + 8) * Nc + gn) = v1;
            }
            if (SDOT) {
                float a0 = ap[col], a1 = ap[col + 1];
                float d0 = dp[col], d1 = dp[col + 1];
                s0s += v0.x * a0 + v0.y * a1;
                s0d += v0.x * d0 + v0.y * d1;
                s1s += v1.x * a0 + v1.y * a1;
                s1d += v1.x * d0 + v1.y * d1;
            }
        }
        if (SDOT) {
#pragma unroll
            for (int o = 1; o <= 2; o <<= 1) {
                s0s += __shfl_xor_sync(0xffffffffu, s0s, o);
                s0d += __shfl_xor_sync(0xffffffffu, s0d, o);
                s1s += __shfl_xor_sync(0xffffffffu, s1s, o);
                s1d += __shfl_xor_sync(0xffffffffu, s1d, o);
            }
            if (qc == 0) {
                int r0 = wm + mi * 16 + qr;
                atomicAdd(&red_s[r0], s0s);
                atomicAdd(&red_d[r0], s0d);
                atomicAdd(&red_s[r0 + 8], s1s);
                atomicAdd(&red_d[r0 + 8], s1d);
            }
        }
    }

    if (SDOT) {
        __syncthreads();
        if (tid < 128) {
            int gm = m0 + tid;
            if (gm < M) {
                ssrc[gm * HH + blockIdx.x] = red_s[tid];
                sdst[gm * HH + blockIdx.x] = red_d[tid];
            }
        }
    }
}

// ---------------- fused GAT aggregation (fp16 gather) + bias + LN + ELU ----------
__global__ __launch_bounds__(128) void gat_aggregate(
    const int* __restrict__ rowptr, const int* __restrict__ csr,
    const float* __restrict__ ssrc, const float* __restrict__ sdst,
    const __half* __restrict__ feat, float* __restrict__ outb,
    const float* __restrict__ bias, const float* __restrict__ g,
    const float* __restrict__ be)
{
    int n = blockIdx.x, t = threadIdx.x;
    int h = t >> 5, lane = t & 31;
    int beg = rowptr[n], end = rowptr[n + 1];

    float sd = sdst[n * HH + h];
    float m = -INFINITY, l = 0.0f;
    float4 acc = make_float4(0.f, 0.f, 0.f, 0.f);
    const __half* fb = feat + h * CC + lane * 4;

    int sNext = csr[beg];
#pragma unroll 1
    for (int j = beg; j < end; j++) {
        int s = sNext;
        if (j + 1 < end) sNext = csr[j + 1];
        float e = ssrc[s * HH + h] + sd;
        e = (e > 0.0f) ? e : NEG_SLOPE * e;
        float mn = fmaxf(m, e);
        float sc = __expf(m - mn);
        float p  = __expf(e - mn);
        uint2 raw = *(const uint2*)(fb + (size_t)s * DD);
        float2 f01 = __half22float2(*(__half2*)&raw.x);
        float2 f23 = __half22float2(*(__half2*)&raw.y);
        acc.x = acc.x * sc + p * f01.x;
        acc.y = acc.y * sc + p * f01.y;
        acc.z = acc.z * sc + p * f23.x;
        acc.w = acc.w * sc + p * f23.y;
        l = l * sc + p;
        m = mn;
    }

    float inv = 1.0f / l;
    float4 bb = ((const float4*)bias)[t];
    float4 x;
    x.x = acc.x * inv + bb.x;
    x.y = acc.y * inv + bb.y;
    x.z = acc.z * inv + bb.z;
    x.w = acc.w * inv + bb.w;

    __shared__ float sm[4];
    float s1 = x.x + x.y + x.z + x.w;
#pragma unroll
    for (int o = 16; o > 0; o >>= 1) s1 += __shfl_down_sync(0xffffffffu, s1, o);
    if (lane == 0) sm[h] = s1;
    __syncthreads();
    float mu = (sm[0] + sm[1] + sm[2] + sm[3]) * (1.0f / DD);
    __syncthreads();

    float dx = x.x - mu, dy = x.y - mu, dz = x.z - mu, dw = x.w - mu;
    float ss = dx * dx + dy * dy + dz * dz + dw * dw;
#pragma unroll
    for (int o = 16; o > 0; o >>= 1) ss += __shfl_down_sync(0xffffffffu, ss, o);
    if (lane == 0) sm[h] = ss;
    __syncthreads();
    float var = (sm[0] + sm[1] + sm[2] + sm[3]) * (1.0f / DD);
    float r = rsqrtf(var + LN_EPS);

    float4 gg = ((const float4*)g)[t];
    float4 b2 = ((const float4*)be)[t];
    float4 y;
    y.x = dx * r * gg.x + b2.x;
    y.y = dy * r * gg.y + b2.y;
    y.z = dz * r * gg.z + b2.z;
    y.w = dw * r * gg.w + b2.w;
    y.x = (y.x > 0.f) ? y.x : expm1f(y.x);
    y.y = (y.y > 0.f) ? y.y : expm1f(y.y);
    y.z = (y.z > 0.f) ? y.z : expm1f(y.z);
    y.w = (y.w > 0.f) ? y.w : expm1f(y.w);
    ((float4*)(outb + (size_t)n * DD))[t] = y;
}

// ---------------- final tiny projection ----------------
__global__ void final_proj(const float* __restrict__ z, const float* __restrict__ Wc2,
                           const float* __restrict__ bc2, float* __restrict__ out)
{
    int gw = (blockIdx.x * blockDim.x + threadIdx.x) >> 5;
    int lane = threadIdx.x & 31;
    if (gw >= NN) return;
    const float* zp = z + (size_t)gw * DD;
    float s0 = 0.f, s1 = 0.f;
    for (int k = lane; k < DD; k += 32) {
        float zv = zp[k];
        s0 += zv * Wc2[2 * k];
        s1 += zv * Wc2[2 * k + 1];
    }
#pragma unroll
    for (int o = 16; o > 0; o >>= 1) {
        s0 += __shfl_down_sync(0xffffffffu, s0, o);
        s1 += __shfl_down_sync(0xffffffffu, s1, o);
    }
    if (lane == 0) { out[gw * 2] = s0 + bc2[0]; out[gw * 2 + 1] = s1 + bc2[1]; }
}

// ---------------- host orchestration ----------------
extern "C" void kernel_launch(void* const* d_in, const int* in_sizes, int n_in,
                              void* d_out, int out_size)
{
    const float* x   = (const float*)d_in[0];
    const void*  ei  = d_in[1];
    const float* W1  = (const float*)d_in[2];
    const float* as1 = (const float*)d_in[3];
    const float* ad1 = (const float*)d_in[4];
    const float* b1  = (const float*)d_in[5];
    const float* g1  = (const float*)d_in[6];
    const float* be1 = (const float*)d_in[7];
    const float* W2  = (const float*)d_in[8];
    const float* as2 = (const float*)d_in[9];
    const float* ad2 = (const float*)d_in[10];
    const float* b2  = (const float*)d_in[11];
    const float* g2  = (const float*)d_in[12];
    const float* be2 = (const float*)d_in[13];
    const float* Wc1 = (const float*)d_in[14];
    const float* bc1 = (const float*)d_in[15];
    const float* Wc2 = (const float*)d_in[16];
    const float* bc2 = (const float*)d_in[17];
    float* out = (float*)d_out;

    float *A, *B, *ssrc, *sdst;
    __half* Hf;
    int *rowptr, *cursor, *bsum, *csr;
    cudaGetSymbolAddress((void**)&A,      g_bufA);
    cudaGetSymbolAddress((void**)&B,      g_bufB);
    cudaGetSymbolAddress((void**)&Hf,     g_half);
    cudaGetSymbolAddress((void**)&ssrc,   g_ssrc);
    cudaGetSymbolAddress((void**)&sdst,   g_sdst);
    cudaGetSymbolAddress((void**)&rowptr, g_rowptr);
    cudaGetSymbolAddress((void**)&cursor, g_cursor);
    cudaGetSymbolAddress((void**)&bsum,   g_bsum);
    cudaGetSymbolAddress((void**)&csr,    g_csr);

    dim3 gemm_grid(DD / 128, (NN + 127) / 128);
    int nb = (NN + 1023) / 1024;

    // launch order arranged so gemm_tf32 is the 4th launch (ncu -s window)
    init_deg<<<(NN + 255) / 256, 256>>>(rowptr);
    detect_idx_width<<<1, 256>>>((const unsigned*)ei);
    count_deg<<<1184, 512>>>(ei, rowptr);

    // layer 1 GEMM: h1 (fp16) + fused attention dots
    gemm_tf32<0, 1, 1><<<gemm_grid, 256>>>(x, W1, nullptr, Hf, NN, FIN, DD,
                                           nullptr, 0, as1, ad1, ssrc, sdst);

    scan1<<<nb, 1024>>>(rowptr, bsum);
    scan2<<<1, 32>>>(bsum, nb);
    scan3<<<(NN + 255) / 256, 256>>>(rowptr, bsum, cursor);
    fill_csr<<<1184, 512>>>(ei, cursor, csr);

    gat_aggregate<<<NN, 128>>>(rowptr, csr, ssrc, sdst, Hf, B, b1, g1, be1);

    // layer 2
    gemm_tf32<1, 1, 1><<<gemm_grid, 256>>>(B, W2, nullptr, Hf, NN, DD, DD,
                                           nullptr, 0, as2, ad2, ssrc, sdst);
    gat_aggregate<<<NN, 128>>>(rowptr, csr, ssrc, sdst, Hf, B, b2, g2, be2);

    // classifier
    gemm_tf32<1, 0, 0><<<gemm_grid, 256>>>(B, Wc1, A, nullptr, NN, DD, DD,
                                           bc1, 1, nullptr, nullptr, nullptr, nullptr);
    final_proj<<<(NN * 32 + 255) / 256, 256>>>(A, Wc2, bc2, out);
}

// round 10
// speedup vs baseline: 4.2211x; 1.4608x over previous
#include <cuda_runtime.h>
#include <cuda_fp16.h>
#include <math.h>

#define NN   100000
#define EE   1600000
#define ENE  1700000      // E + N self loops
#define HH   4
#define CC   128
#define DD   512
#define FIN  182
#define FINP 192          // FIN padded to 32-multiple for B tiles
#define NEG_SLOPE 0.2f
#define LN_EPS 1e-5f

// ---------------- scratch (device globals) ----------------
__device__ __half g_half[(size_t)NN * DD];    // h features (gather src), later z
__device__ __half g_feat[(size_t)NN * DD];    // LN'd features f1/f2 (GEMM A input)
__device__ __half g_w1h[FINP * DD];
__device__ __half g_w2h[DD * DD];
__device__ __half g_wc1h[DD * DD];
__device__ float  g_ssrc[NN * HH];
__device__ float  g_sdst[NN * HH];
__device__ int    g_rowptr[NN + 1];
__device__ int    g_cursor[NN];
__device__ int    g_bsum[256];
__device__ int    g_csr[ENE];
__device__ int    g_is64;

// ---------------- edge decode ----------------
__device__ __forceinline__ void load_edge(const void* ei, int ed, int& s, int& d) {
    if (ed >= EE) { s = d = ed - EE; return; }
    if (g_is64) {
        const long long* p = (const long long*)ei;
        s = (int)p[ed]; d = (int)p[EE + ed];
    } else {
        const int* p = (const int*)ei;
        s = p[ed]; d = p[EE + ed];
    }
}

__global__ void detect_idx_width(const unsigned* __restrict__ w) {
    __shared__ unsigned acc[256];
    unsigned v = 0;
    for (int i = threadIdx.x; i < 4096; i += 256)
        if (i & 1) v |= w[i];
    acc[threadIdx.x] = v;
    __syncthreads();
    for (int s = 128; s > 0; s >>= 1) {
        if (threadIdx.x < s) acc[threadIdx.x] |= acc[threadIdx.x + s];
        __syncthreads();
    }
    if (threadIdx.x == 0) g_is64 = (acc[0] == 0u) ? 1 : 0;
}

// ---------------- weight conversion fp32 -> fp16 (zero-padded) ----------------
__global__ void convert_w(const float* __restrict__ s, __half* __restrict__ d,
                          int n, int ntot) {
    int i = blockIdx.x * blockDim.x + threadIdx.x;
    if (i < ntot) d[i] = (i < n) ? __float2half(s[i]) : __float2half(0.0f);
}

// ---------------- CSR build ----------------
__global__ void init_deg(int* __restrict__ deg) {
    int i = blockIdx.x * blockDim.x + threadIdx.x;
    if (i < NN) deg[i] = 1;
}

__global__ void count_deg(const void* __restrict__ ei, int* __restrict__ deg) {
    for (int ed = blockIdx.x * blockDim.x + threadIdx.x; ed < EE;
         ed += gridDim.x * blockDim.x) {
        int s, d; load_edge(ei, ed, s, d);
        atomicAdd(&deg[d], 1);
    }
}

__global__ __launch_bounds__(1024) void scan1(int* __restrict__ rp, int* __restrict__ bsum) {
    __shared__ int sh[1024];
    int i = blockIdx.x * 1024 + threadIdx.x;
    int v = (i < NN) ? rp[i] : 0;
    sh[threadIdx.x] = v;
    __syncthreads();
#pragma unroll
    for (int o = 1; o < 1024; o <<= 1) {
        int t = (threadIdx.x >= o) ? sh[threadIdx.x - o] : 0;
        __syncthreads();
        sh[threadIdx.x] += t;
        __syncthreads();
    }
    if (i < NN) rp[i] = sh[threadIdx.x] - v;
    if (threadIdx.x == 1023) bsum[blockIdx.x] = sh[1023];
}

__global__ void scan2(int* __restrict__ bsum, int nb) {
    if (threadIdx.x == 0) {
        int acc = 0;
        for (int i = 0; i < nb; i++) { int t = bsum[i]; bsum[i] = acc; acc += t; }
    }
}

__global__ void scan3(int* __restrict__ rp, const int* __restrict__ bsum,
                      int* __restrict__ cursor) {
    int i = blockIdx.x * blockDim.x + threadIdx.x;
    if (i < NN) {
        int v = rp[i] + bsum[i >> 10];
        rp[i] = v;
        cursor[i] = v;
    }
    if (i == 0) rp[NN] = ENE;
}

__global__ void fill_csr(const void* __restrict__ ei, int* __restrict__ cursor,
                         int* __restrict__ csr) {
    for (int ed = blockIdx.x * blockDim.x + threadIdx.x; ed < ENE;
         ed += gridDim.x * blockDim.x) {
        int s, d; load_edge(ei, ed, s, d);
        int pos = atomicAdd(&cursor[d], 1);
        csr[pos] = s;
    }
}

// ---------------- fp16 tensor-core GEMM (ldmatrix + cp.async) ----------------
__device__ __forceinline__ void mma_f16(float (&c)[4], const unsigned (&a)[4],
                                        const unsigned (&b)[2]) {
    asm volatile(
        "mma.sync.aligned.m16n8k16.row.col.f32.f16.f16.f32 "
        "{%0,%1,%2,%3}, {%4,%5,%6,%7}, {%8,%9}, {%0,%1,%2,%3};"
        : "+f"(c[0]), "+f"(c[1]), "+f"(c[2]), "+f"(c[3])
        : "r"(a[0]), "r"(a[1]), "r"(a[2]), "r"(a[3]), "r"(b[0]), "r"(b[1]));
}

__device__ __forceinline__ void ldsm_x4(unsigned& r0, unsigned& r1, unsigned& r2,
                                        unsigned& r3, unsigned addr) {
    asm volatile("ldmatrix.sync.aligned.m8n8.x4.shared.b16 {%0,%1,%2,%3}, [%4];"
                 : "=r"(r0), "=r"(r1), "=r"(r2), "=r"(r3) : "r"(addr));
}

__device__ __forceinline__ void ldsm_x4t(unsigned& r0, unsigned& r1, unsigned& r2,
                                         unsigned& r3, unsigned addr) {
    asm volatile("ldmatrix.sync.aligned.m8n8.x4.trans.shared.b16 {%0,%1,%2,%3}, [%4];"
                 : "=r"(r0), "=r"(r1), "=r"(r2), "=r"(r3) : "r"(addr));
}

__device__ __forceinline__ void cp16(unsigned dst, const void* src, int szbytes) {
    asm volatile("cp.async.ca.shared.global [%0], [%1], 16, %2;"
                 :: "r"(dst), "l"(src), "r"(szbytes));
}
#define CP_COMMIT() asm volatile("cp.async.commit_group;")
#define CP_WAIT0()  asm volatile("cp.async.wait_group 0;")

#define APAD 40    // A row stride in halves (32 + 8)
#define BPAD 136   // B row stride in halves (128 + 8)

// C[M,Nc] = A[M,K] @ B[K,Nc] (+bias)(+relu), fp16 out.
// 128x128 tile, BK=32, 256 thr, 8 warps of 64x32, 2-stage cp.async pipeline.
// L1A: A is fp32 (layer 1, K=182, unaligned) staged via registers.
// SDOT: emit ssrc/sdst (head = blockIdx.x) from fp32 accumulators.
template <int L1A, int SDOT>
__global__ __launch_bounds__(256) void gemm_h(
    const float* __restrict__ Af, const __half* __restrict__ Ah,
    const __half* __restrict__ Bh, __half* __restrict__ Ch,
    int M, int K, int Nc, const float* __restrict__ bias, int doRelu,
    const float* __restrict__ asrc, const float* __restrict__ adst,
    float* __restrict__ ssrc, float* __restrict__ sdst)
{
    __shared__ __align__(16) __half As[2][128][APAD];
    __shared__ __align__(16) __half Bs[2][32][BPAD];
    __shared__ float red_s[128], red_d[128];

    int tid = threadIdx.x;
    int warp = tid >> 5, lane = tid & 31;
    int qr = lane >> 2, qc = lane & 3;
    int m0 = blockIdx.y * 128, n0 = blockIdx.x * 128;
    int wm = (warp >> 2) * 64;
    int wn = (warp & 3) * 32;

    float c[4][4][4];
#pragma unroll
    for (int i = 0; i < 4; i++)
#pragma unroll
        for (int j = 0; j < 4; j++)
#pragma unroll
            for (int k = 0; k < 4; k++) c[i][j][k] = 0.0f;

    if (SDOT && tid < 128) { red_s[tid] = 0.0f; red_d[tid] = 0.0f; }

    // staging thread mapping
    int a_row = tid & 127, a_seg = tid >> 7;        // A: 2 thr/row, 16 halves each
    int b_k   = tid >> 3,  b_n  = (tid & 7) * 16;   // B: 8 thr/k-row, 16 halves each

    float a_st[16];                                  // L1A only
    int kt = (K + 31) / 32;

    auto issue = [&](int t) {
        int buf = t & 1;
        int k0 = t * 32;
        if (L1A) {
            int gm = m0 + a_row;
#pragma unroll
            for (int j = 0; j < 16; j++) {
                int gk = k0 + a_seg * 16 + j;
                a_st[j] = (gm < M && gk < K) ? Af[(size_t)gm * K + gk] : 0.0f;
            }
        } else {
            int gm = m0 + a_row;
            unsigned dst = (unsigned)__cvta_generic_to_shared(&As[buf][a_row][a_seg * 16]);
            const __half* src = Ah + (size_t)gm * K + k0 + a_seg * 16;
            int sz = (gm < M) ? 16 : 0;
            cp16(dst, src, sz);
            cp16(dst + 16, src + 8, sz);
        }
        {
            unsigned dst = (unsigned)__cvta_generic_to_shared(&Bs[buf][b_k][b_n]);
            const __half* src = Bh + (size_t)(k0 + b_k) * Nc + n0 + b_n;
            cp16(dst, src, 16);
            cp16(dst + 16, src + 8, 16);
        }
    };
    auto sts_a = [&](int buf) {
#pragma unroll
        for (int j = 0; j < 16; j += 2)
            *(__half2*)&As[buf][a_row][a_seg * 16 + j] =
                __floats2half2_rn(a_st[j], a_st[j + 1]);
    };

    issue(0);
    if (L1A) sts_a(0);
    CP_COMMIT();

    // ldmatrix lane addressing (constant per thread)
    int lm_row = lane & 15;
    int lm_kof = (lane >> 4) << 3;

    for (int t = 0; t < kt; t++) {
        CP_WAIT0();
        __syncthreads();
        int cur = t & 1;
        if (t + 1 < kt) { issue(t + 1); CP_COMMIT(); }

#pragma unroll
        for (int s = 0; s < 2; s++) {
            int ks = s * 16;
            unsigned b[4][2];
            {
                unsigned addr0 = (unsigned)__cvta_generic_to_shared(
                    &Bs[cur][ks + lm_row][wn + lm_kof]);
                ldsm_x4t(b[0][0], b[0][1], b[1][0], b[1][1], addr0);
                unsigned addr1 = (unsigned)__cvta_generic_to_shared(
                    &Bs[cur][ks + lm_row][wn + 16 + lm_kof]);
                ldsm_x4t(b[2][0], b[2][1], b[3][0], b[3][1], addr1);
            }
#pragma unroll
            for (int mi = 0; mi < 4; mi++) {
                unsigned a[4];
                unsigned addr = (unsigned)__cvta_generic_to_shared(
                    &As[cur][wm + mi * 16 + lm_row][ks + lm_kof]);
                ldsm_x4(a[0], a[1], a[2], a[3], addr);
#pragma unroll
                for (int nj = 0; nj < 4; nj++)
                    mma_f16(c[mi][nj], a, b[nj]);
            }
        }

        if (L1A && t + 1 < kt) sts_a((t + 1) & 1);
    }

    // ---- epilogue: fp16 store (+bias/relu), fused attention dots ----
    const float* ap = SDOT ? (asrc + blockIdx.x * CC) : nullptr;
    const float* dp = SDOT ? (adst + blockIdx.x * CC) : nullptr;

#pragma unroll
    for (int mi = 0; mi < 4; mi++) {
        float s0s = 0.f, s0d = 0.f, s1s = 0.f, s1d = 0.f;
#pragma unroll
        for (int nj = 0; nj < 4; nj++) {
            int gm0 = m0 + wm + mi * 16 + qr;
            int col = wn + nj * 8 + 2 * qc;
            int gn  = n0 + col;
            float2 v0 = make_float2(c[mi][nj][0], c[mi][nj][1]);
            float2 v1 = make_float2(c[mi][nj][2], c[mi][nj][3]);
            if (bias) {
                float bx = bias[gn], by = bias[gn + 1];
                v0.x += bx; v0.y += by; v1.x += bx; v1.y += by;
            }
            if (doRelu) {
                v0.x = fmaxf(v0.x, 0.f); v0.y = fmaxf(v0.y, 0.f);
                v1.x = fmaxf(v1.x, 0.f); v1.y = fmaxf(v1.y, 0.f);
            }
            if (gm0 < M)
                *(__half2*)(Ch + (size_t)gm0 * Nc + gn) = __floats2half2_rn(v0.x, v0.y);
            if (gm0 + 8 < M)
                *(__half2*)(Ch + (size_t)(gm0 + 8) * Nc + gn) = __floats2half2_rn(v1.x, v1.y);
            if (SDOT) {
                float a0 = ap[col], a1 = ap[col + 1];
                float d0 = dp[col], d1 = dp[col + 1];
                s0s += v0.x * a0 + v0.y * a1;
                s0d += v0.x * d0 + v0.y * d1;
                s1s += v1.x * a0 + v1.y * a1;
                s1d += v1.x * d0 + v1.y * d1;
            }
        }
        if (SDOT) {
#pragma unroll
            for (int o = 1; o <= 2; o <<= 1) {
                s0s += __shfl_xor_sync(0xffffffffu, s0s, o);
                s0d += __shfl_xor_sync(0xffffffffu, s0d, o);
                s1s += __shfl_xor_sync(0xffffffffu, s1s, o);
                s1d += __shfl_xor_sync(0xffffffffu, s1d, o);
            }
            if (qc == 0) {
                int r0 = wm + mi * 16 + qr;
                atomicAdd(&red_s[r0], s0s);
                atomicAdd(&red_d[r0], s0d);
                atomicAdd(&red_s[r0 + 8], s1s);
                atomicAdd(&red_d[r0 + 8], s1d);
            }
        }
    }

    if (SDOT) {
        __syncthreads();
        if (tid < 128) {
            int gm = m0 + tid;
            if (gm < M) {
                ssrc[gm * HH + blockIdx.x] = red_s[tid];
                sdst[gm * HH + blockIdx.x] = red_d[tid];
            }
        }
    }
}

// ---------------- fused GAT aggregation (fp16 gather) + bias + LN + ELU ----------
__global__ __launch_bounds__(128) void gat_aggregate(
    const int* __restrict__ rowptr, const int* __restrict__ csr,
    const float* __restrict__ ssrc, const float* __restrict__ sdst,
    const __half* __restrict__ feat, __half* __restrict__ outh,
    const float* __restrict__ bias, const float* __restrict__ g,
    const float* __restrict__ be)
{
    int n = blockIdx.x, t = threadIdx.x;
    int h = t >> 5, lane = t & 31;
    int beg = rowptr[n], end = rowptr[n + 1];

    float sd = sdst[n * HH + h];
    float m = -INFINITY, l = 0.0f;
    float4 acc = make_float4(0.f, 0.f, 0.f, 0.f);
    const __half* fb = feat + h * CC + lane * 4;

    int sNext = csr[beg];
#pragma unroll 1
    for (int j = beg; j < end; j++) {
        int s = sNext;
        if (j + 1 < end) sNext = csr[j + 1];
        float e = ssrc[s * HH + h] + sd;
        e = (e > 0.0f) ? e : NEG_SLOPE * e;
        float mn = fmaxf(m, e);
        float sc = __expf(m - mn);
        float p  = __expf(e - mn);
        uint2 raw = *(const uint2*)(fb + (size_t)s * DD);
        float2 f01 = __half22float2(*(__half2*)&raw.x);
        float2 f23 = __half22float2(*(__half2*)&raw.y);
        acc.x = acc.x * sc + p * f01.x;
        acc.y = acc.y * sc + p * f01.y;
        acc.z = acc.z * sc + p * f23.x;
        acc.w = acc.w * sc + p * f23.y;
        l = l * sc + p;
        m = mn;
    }

    float inv = 1.0f / l;
    float4 bb = ((const float4*)bias)[t];
    float4 x;
    x.x = acc.x * inv + bb.x;
    x.y = acc.y * inv + bb.y;
    x.z = acc.z * inv + bb.z;
    x.w = acc.w * inv + bb.w;

    __shared__ float sm[4];
    float s1 = x.x + x.y + x.z + x.w;
#pragma unroll
    for (int o = 16; o > 0; o >>= 1) s1 += __shfl_down_sync(0xffffffffu, s1, o);
    if (lane == 0) sm[h] = s1;
    __syncthreads();
    float mu = (sm[0] + sm[1] + sm[2] + sm[3]) * (1.0f / DD);
    __syncthreads();

    float dx = x.x - mu, dy = x.y - mu, dz = x.z - mu, dw = x.w - mu;
    float ss = dx * dx + dy * dy + dz * dz + dw * dw;
#pragma unroll
    for (int o = 16; o > 0; o >>= 1) ss += __shfl_down_sync(0xffffffffu, ss, o);
    if (lane == 0) sm[h] = ss;
    __syncthreads();
    float var = (sm[0] + sm[1] + sm[2] + sm[3]) * (1.0f / DD);
    float r = rsqrtf(var + LN_EPS);

    float4 gg = ((const float4*)g)[t];
    float4 b2 = ((const float4*)be)[t];
    float4 y;
    y.x = dx * r * gg.x + b2.x;
    y.y = dy * r * gg.y + b2.y;
    y.z = dz * r * gg.z + b2.z;
    y.w = dw * r * gg.w + b2.w;
    y.x = (y.x > 0.f) ? y.x : expm1f(y.x);
    y.y = (y.y > 0.f) ? y.y : expm1f(y.y);
    y.z = (y.z > 0.f) ? y.z : expm1f(y.z);
    y.w = (y.w > 0.f) ? y.w : expm1f(y.w);

    __half2* op = (__half2*)(outh + (size_t)n * DD + t * 4);
    op[0] = __floats2half2_rn(y.x, y.y);
    op[1] = __floats2half2_rn(y.z, y.w);
}

// ---------------- final tiny projection (fp16 z) ----------------
__global__ void final_proj(const __half* __restrict__ z, const float* __restrict__ Wc2,
                           const float* __restrict__ bc2, float* __restrict__ out)
{
    int gw = (blockIdx.x * blockDim.x + threadIdx.x) >> 5;
    int lane = threadIdx.x & 31;
    if (gw >= NN) return;
    const __half* zp = z + (size_t)gw * DD;
    float s0 = 0.f, s1 = 0.f;
    for (int k = lane; k < DD; k += 32) {
        float zv = __half2float(zp[k]);
        s0 += zv * Wc2[2 * k];
        s1 += zv * Wc2[2 * k + 1];
    }
#pragma unroll
    for (int o = 16; o > 0; o >>= 1) {
        s0 += __shfl_down_sync(0xffffffffu, s0, o);
        s1 += __shfl_down_sync(0xffffffffu, s1, o);
    }
    if (lane == 0) { out[gw * 2] = s0 + bc2[0]; out[gw * 2 + 1] = s1 + bc2[1]; }
}

// ---------------- host orchestration ----------------
extern "C" void kernel_launch(void* const* d_in, const int* in_sizes, int n_in,
                              void* d_out, int out_size)
{
    const float* x   = (const float*)d_in[0];
    const void*  ei  = d_in[1];
    const float* W1  = (const float*)d_in[2];
    const float* as1 = (const float*)d_in[3];
    const float* ad1 = (const float*)d_in[4];
    const float* b1  = (const float*)d_in[5];
    const float* g1  = (const float*)d_in[6];
    const float* be1 = (const float*)d_in[7];
    const float* W2  = (const float*)d_in[8];
    const float* as2 = (const float*)d_in[9];
    const float* ad2 = (const float*)d_in[10];
    const float* b2  = (const float*)d_in[11];
    const float* g2  = (const float*)d_in[12];
    const float* be2 = (const float*)d_in[13];
    const float* Wc1 = (const float*)d_in[14];
    const float* bc1 = (const float*)d_in[15];
    const float* Wc2 = (const float*)d_in[16];
    const float* bc2 = (const float*)d_in[17];
    float* out = (float*)d_out;

    __half *Hf, *Ff, *W1h, *W2h, *Wc1h;
    float *ssrc, *sdst;
    int *rowptr, *cursor, *bsum, *csr;
    cudaGetSymbolAddress((void**)&Hf,     g_half);
    cudaGetSymbolAddress((void**)&Ff,     g_feat);
    cudaGetSymbolAddress((void**)&W1h,    g_w1h);
    cudaGetSymbolAddress((void**)&W2h,    g_w2h);
    cudaGetSymbolAddress((void**)&Wc1h,   g_wc1h);
    cudaGetSymbolAddress((void**)&ssrc,   g_ssrc);
    cudaGetSymbolAddress((void**)&sdst,   g_sdst);
    cudaGetSymbolAddress((void**)&rowptr, g_rowptr);
    cudaGetSymbolAddress((void**)&cursor, g_cursor);
    cudaGetSymbolAddress((void**)&bsum,   g_bsum);
    cudaGetSymbolAddress((void**)&csr,    g_csr);

    dim3 gemm_grid(DD / 128, (NN + 127) / 128);
    int nb = (NN + 1023) / 1024;

    // gemm_h is the 4th launch (profiler window)
    convert_w<<<(FINP * DD + 255) / 256, 256>>>(W1, W1h, FIN * DD, FINP * DD);
    init_deg<<<(NN + 255) / 256, 256>>>(rowptr);
    detect_idx_width<<<1, 256>>>((const unsigned*)ei);

    // layer 1 GEMM: h1 (fp16) + fused attention dots
    gemm_h<1, 1><<<gemm_grid, 256>>>(x, nullptr, W1h, Hf, NN, FIN, DD,
                                     nullptr, 0, as1, ad1, ssrc, sdst);

    count_deg<<<1184, 512>>>(ei, rowptr);
    convert_w<<<(DD * DD + 255) / 256, 256>>>(W2, W2h, DD * DD, DD * DD);
    convert_w<<<(DD * DD + 255) / 256, 256>>>(Wc1, Wc1h, DD * DD, DD * DD);
    scan1<<<nb, 1024>>>(rowptr, bsum);
    scan2<<<1, 32>>>(bsum, nb);
    scan3<<<(NN + 255) / 256, 256>>>(rowptr, bsum, cursor);
    fill_csr<<<1184, 512>>>(ei, cursor, csr);

    gat_aggregate<<<NN, 128>>>(rowptr, csr, ssrc, sdst, Hf, Ff, b1, g1, be1);

    // layer 2
    gemm_h<0, 1><<<gemm_grid, 256>>>(nullptr, Ff, W2h, Hf, NN, DD, DD,
                                     nullptr, 0, as2, ad2, ssrc, sdst);
    gat_aggregate<<<NN, 128>>>(rowptr, csr, ssrc, sdst, Hf, Ff, b2, g2, be2);

    // classifier: z = relu(f2 @ Wc1 + bc1) -> reuse Hf for z
    gemm_h<0, 0><<<gemm_grid, 256>>>(nullptr, Ff, Wc1h, Hf, NN, DD, DD,
                                     bc1, 1, nullptr, nullptr, nullptr, nullptr);
    final_proj<<<(NN * 32 + 255) / 256, 256>>>(Hf, Wc2, bc2, out);
}